// round 5
// baseline (speedup 1.0000x reference)
#include <cuda_runtime.h>
#include <cstdint>

#define NB 4096
#define NS 64
#define ND 512
#define NDEPTH 4
#define VOCAB 2
#define LN_EPS 1e-5f

#define BM 128
#define BN 64
#define BK 32
#define ROWF 36  // 32 data + 4 pad floats per smem row (144B, conflict-free LDS.128)

#define GBLK 256
#define GTHR 256

#define A_BUF_F (BM * ROWF)         // 4608 floats per A buffer
#define B_OFF_F (2 * A_BUF_F)       // 9216
#define B_BUF_F (BN * ROWF)         // 2304 floats per B buffer
#define SMEM_F (B_OFF_F + 2 * B_BUF_F)  // 13824 floats = 55296 B

#define F_RND 1
#define F_RELU 2
#define F_RES 4

// Activation scratch (sigma-permuted storage order)
static __device__ __align__(128) float g_x[NB * ND];
static __device__ __align__(128) float g_y[NB * ND];
static __device__ __align__(128) float g_v[NB * ND];
static __device__ __align__(128) float g_h[NB * 4 * ND];
// Pre-rounded, transposed, doubly-permuted weights: [l][n_st][k_st]
static __device__ __align__(128) float g_wv[NDEPTH * ND * ND];
static __device__ __align__(128) float g_wo[NDEPTH * ND * ND];
static __device__ __align__(128) float g_w1[NDEPTH * 4 * ND * ND];
static __device__ __align__(128) float g_w2[NDEPTH * 4 * ND * ND];
// Permuted small params
static __device__ float g_ln1g[NDEPTH * ND], g_ln1b[NDEPTH * ND];
static __device__ float g_ln2g[NDEPTH * ND], g_ln2b[NDEPTH * ND];
static __device__ float g_bv[NDEPTH * ND], g_bo[NDEPTH * ND];
static __device__ float g_b1[NDEPTH * 4 * ND], g_b2[NDEPTH * ND];
static __device__ float g_emb[VOCAB * ND], g_ss[ND], g_hw[ND * 2];

static __device__ unsigned g_bar = 0;
static __device__ volatile unsigned g_epoch = 0;

__device__ __forceinline__ void grid_bar() {
    __threadfence();
    __syncthreads();
    if (threadIdx.x == 0) {
        unsigned e = g_epoch;
        if (atomicAdd(&g_bar, 1u) == GBLK - 1) {
            g_bar = 0;
            __threadfence();
            g_epoch = e + 1;
        } else {
            while (g_epoch == e) __nanosleep(32);
            __threadfence();
        }
    }
    __syncthreads();
}

__device__ __forceinline__ float warp_sum(float v) {
#pragma unroll
    for (int o = 16; o > 0; o >>= 1) v += __shfl_xor_sync(0xffffffffu, v, o);
    return v;
}

__device__ __forceinline__ float rnaf(float f) {
    uint32_t r;
    asm("cvt.rna.tf32.f32 %0, %1;" : "=r"(r) : "f"(f));
    return __uint_as_float(r);
}

// storage word w holds logical feature sig(w); sig within each 32-block
__device__ __forceinline__ int sig(int i) {
    int w = i & 31;
    return (i & ~31) | ((w >> 3) | ((w & 7) << 2));
}

__device__ __forceinline__ void cpasync16(void* smem, const void* gmem) {
    uint32_t sa = (uint32_t)__cvta_generic_to_shared(smem);
    asm volatile("cp.async.cg.shared.global [%0], [%1], 16;\n" ::"r"(sa), "l"(gmem));
}

// ---------------------------------------------------------------------------
// One-time prep: RNA-round + transpose + double-sigma-permute weights,
// sigma-permute all small params.
// ---------------------------------------------------------------------------
__device__ void prep_phase(const float* __restrict__ qkv_w, const float* __restrict__ out_w,
                           const float* __restrict__ ff1_w, const float* __restrict__ ff2_w,
                           const float* __restrict__ ln1_g, const float* __restrict__ ln1_b,
                           const float* __restrict__ ln2_g, const float* __restrict__ ln2_b,
                           const float* __restrict__ qkv_b, const float* __restrict__ out_b,
                           const float* __restrict__ ff1_b, const float* __restrict__ ff2_b,
                           const float* __restrict__ bit_emb, const float* __restrict__ start,
                           const float* __restrict__ head_w) {
    const int tid = blockIdx.x * GTHR + threadIdx.x;
    const int stride = GBLK * GTHR;
    for (int i = tid; i < NDEPTH * ND * ND; i += stride) {
        int k = i & (ND - 1), n = (i >> 9) & (ND - 1), l = i >> 18;
        g_wv[i] = rnaf(qkv_w[((size_t)l * ND + sig(k)) * (3 * ND) + 2 * ND + sig(n)]);
        g_wo[i] = rnaf(out_w[((size_t)l * ND + sig(k)) * ND + sig(n)]);
    }
    for (int i = tid; i < NDEPTH * 4 * ND * ND; i += stride) {
        int k = i & (ND - 1), n = (i >> 9) & (4 * ND - 1), l = i >> 20;
        g_w1[i] = rnaf(ff1_w[((size_t)l * ND + sig(k)) * (4 * ND) + sig(n)]);
    }
    for (int i = tid; i < NDEPTH * 4 * ND * ND; i += stride) {
        int k = i & (4 * ND - 1), n = (i >> 11) & (ND - 1), l = i >> 20;
        g_w2[i] = rnaf(ff2_w[((size_t)l * 4 * ND + sig(k)) * ND + sig(n)]);
    }
    for (int i = tid; i < NDEPTH * ND; i += stride) {
        int w = i & (ND - 1), l = i >> 9;
        int s = l * ND + sig(w);
        g_ln1g[i] = ln1_g[s];
        g_ln1b[i] = ln1_b[s];
        g_ln2g[i] = ln2_g[s];
        g_ln2b[i] = ln2_b[s];
        g_bv[i] = qkv_b[l * 3 * ND + 2 * ND + sig(w)];
        g_bo[i] = out_b[s];
        g_b2[i] = ff2_b[s];
    }
    for (int i = tid; i < NDEPTH * 4 * ND; i += stride) {
        int w = i & (4 * ND - 1), l = i >> 11;
        g_b1[i] = ff1_b[l * 4 * ND + sig(w)];
    }
    for (int i = tid; i < VOCAB * ND; i += stride) {
        int w = i & (ND - 1), v = i >> 9;
        g_emb[i] = bit_emb[v * ND + sig(w)];
    }
    for (int i = tid; i < ND; i += stride) g_ss[i] = start[sig(i)];
    for (int i = tid; i < 2 * ND; i += stride) g_hw[i] = head_w[sig(i >> 1) * 2 + (i & 1)];
}

// ---------------------------------------------------------------------------
// Elementwise phases (warp per row). All vectors in storage order.
// ---------------------------------------------------------------------------
__device__ void emb0_phase(const int* __restrict__ a_seq, const int* __restrict__ b_seq) {
    int gw = blockIdx.x * 8 + (threadIdx.x >> 5);
    int lane = threadIdx.x & 31;
    for (int row = gw; row < NB; row += GBLK * 8) {
        int a = a_seq[row * NS];
        int b = b_seq[row * NS];
        const float4* ea = (const float4*)(g_emb + (size_t)a * ND);
        const float4* eb = (const float4*)(g_emb + (size_t)b * ND);
        const float4* ss = (const float4*)g_ss;
        float4* xr = (float4*)(g_x + (size_t)row * ND);
#pragma unroll
        for (int j = 0; j < 4; j++) {
            int c = lane + 32 * j;
            float4 va = ea[c], vb = eb[c], vs = ss[c];
            float4 o;
            o.x = va.x + vb.x + vs.x;
            o.y = va.y + vb.y + vs.y;
            o.z = va.z + vb.z + vs.z;
            o.w = va.w + vb.w + vs.w;
            xr[c] = o;
        }
    }
}

__device__ void ln_phase(const float* __restrict__ x, float* __restrict__ y,
                         const float* __restrict__ g, const float* __restrict__ b) {
    int gw = blockIdx.x * 8 + (threadIdx.x >> 5);
    int lane = threadIdx.x & 31;
    for (int row = gw; row < NB; row += GBLK * 8) {
        const float4* xr = (const float4*)(x + (size_t)row * ND);
        float4 v[4];
        float s = 0.f;
#pragma unroll
        for (int j = 0; j < 4; j++) {
            v[j] = xr[lane + 32 * j];
            s += v[j].x + v[j].y + v[j].z + v[j].w;
        }
        s = warp_sum(s);
        float mean = s * (1.0f / ND);
        float q = 0.f;
#pragma unroll
        for (int j = 0; j < 4; j++) {
            float cx = v[j].x - mean, cy = v[j].y - mean;
            float cz = v[j].z - mean, cw = v[j].w - mean;
            q += cx * cx + cy * cy + cz * cz + cw * cw;
        }
        q = warp_sum(q);
        float r = rsqrtf(q * (1.0f / ND) + LN_EPS);
        float4* yr = (float4*)(y + (size_t)row * ND);
#pragma unroll
        for (int j = 0; j < 4; j++) {
            int c = lane + 32 * j;
            float4 gg = ((const float4*)g)[c];
            float4 bb = ((const float4*)b)[c];
            float4 o;
            o.x = rnaf((v[j].x - mean) * r * gg.x + bb.x);
            o.y = rnaf((v[j].y - mean) * r * gg.y + bb.y);
            o.z = rnaf((v[j].z - mean) * r * gg.z + bb.z);
            o.w = rnaf((v[j].w - mean) * r * gg.w + bb.w);
            yr[c] = o;
        }
    }
}

__device__ void heademb_phase(const float* __restrict__ hb, float* __restrict__ out,
                              const int* __restrict__ a_seq, const int* __restrict__ b_seq,
                              int t) {
    int gw = blockIdx.x * 8 + (threadIdx.x >> 5);
    int lane = threadIdx.x & 31;
    for (int row = gw; row < NB; row += GBLK * 8) {
        float4* xr = (float4*)(g_x + (size_t)row * ND);
        float4 v[4];
        float s0 = 0.f, s1 = 0.f;
#pragma unroll
        for (int j = 0; j < 4; j++) {
            int c = lane + 32 * j;
            v[j] = xr[c];
#pragma unroll
            for (int u = 0; u < 4; u++) {
                float xv = (&v[j].x)[u];
                float2 w = ((const float2*)g_hw)[c * 4 + u];
                s0 += xv * w.x;
                s1 += xv * w.y;
            }
        }
        s0 = warp_sum(s0);
        s1 = warp_sum(s1);
        if (lane == 0) {
            out[(size_t)row * NS * 2 + t * 2 + 0] = s0 + hb[0];
            out[(size_t)row * NS * 2 + t * 2 + 1] = s1 + hb[1];
        }
        if (t + 1 < NS) {
            int a = a_seq[row * NS + t + 1];
            int b = b_seq[row * NS + t + 1];
            const float4* ea = (const float4*)(g_emb + (size_t)a * ND);
            const float4* eb = (const float4*)(g_emb + (size_t)b * ND);
#pragma unroll
            for (int j = 0; j < 4; j++) {
                int c = lane + 32 * j;
                float4 va = ea[c], vb = eb[c];
                float4 o = v[j];
                o.x += va.x + vb.x;
                o.y += va.y + vb.y;
                o.z += va.z + vb.z;
                o.w += va.w + vb.w;
                xr[c] = o;
            }
        }
    }
}

// ---------------------------------------------------------------------------
// TF32 GEMM (legacy mma.sync) with sigma-vectorized fragments.
// C = epi(A[M,K] @ Wt^T + bias); Wt = [N,K] storage-order, pre-rounded.
// 128x64 tiles, 8 warps 4x2, warp tile 32x32, mma m16n8k8, cp.async dbuf.
// Per ktile per warp: 16x LDS.128 + 32x HMMA.
// ---------------------------------------------------------------------------
template <int FLAGS>
__device__ void gemm_phase(const float* __restrict__ A, const float* __restrict__ Wt,
                           const float* __restrict__ bias, float* __restrict__ C, int K, int N,
                           float* sm) {
    const int tid = threadIdx.x;
    const int warp = tid >> 5, lane = tid & 31;
    const int wm = warp >> 1, wn = warp & 1;
    const int gid = lane >> 2, tig = lane & 3;

    const int arow0 = wm * 32 + gid;       // A rows: +0, +8, +16, +24
    const int brow0 = wn * 32 + gid;       // B rows: +0, +8, +16, +24 (ni*8)
    const int ntN = N / BN;
    const int ntiles = (NB / BM) * ntN;
    const int KT = K / BK;

    for (int tile = blockIdx.x; tile < ntiles; tile += GBLK) {
        const int bm = tile / ntN, bn = tile % ntN;
        const float* Ag = A + (size_t)bm * BM * K;
        const float* Wg = Wt + (size_t)bn * BN * K;

        float acc[2][4][4];
#pragma unroll
        for (int i = 0; i < 2; i++)
#pragma unroll
            for (int j = 0; j < 4; j++)
#pragma unroll
                for (int k = 0; k < 4; k++) acc[i][j][k] = 0.f;

        auto load_tiles = [&](int kt, int buf) {
            float* dA = sm + buf * A_BUF_F;
            const float* srcA = Ag + kt * BK;
#pragma unroll
            for (int i = 0; i < 4; i++) {
                int c = tid + i * 256;
                int row = c >> 3, ch = c & 7;
                cpasync16(dA + row * ROWF + ch * 4, srcA + (size_t)row * K + ch * 4);
            }
            float* dW = sm + B_OFF_F + buf * B_BUF_F;
            const float* srcW = Wg + kt * BK;
#pragma unroll
            for (int i = 0; i < 2; i++) {
                int c = tid + i * 256;
                int row = c >> 3, ch = c & 7;
                cpasync16(dW + row * ROWF + ch * 4, srcW + (size_t)row * K + ch * 4);
            }
            asm volatile("cp.async.commit_group;\n");
        };

        load_tiles(0, 0);

        for (int kt = 0; kt < KT; ++kt) {
            if (kt + 1 < KT) {
                load_tiles(kt + 1, (kt + 1) & 1);
                asm volatile("cp.async.wait_group 1;\n");
            } else {
                asm volatile("cp.async.wait_group 0;\n");
            }
            __syncthreads();
            const float* a_ = sm + (kt & 1) * A_BUF_F;
            const float* w_ = sm + B_OFF_F + (kt & 1) * B_BUF_F;

            // Preload all fragments: contiguous 8 words per row (storage sigma order)
            float4 aw[4][2], bw[4][2];
#pragma unroll
            for (int r = 0; r < 4; r++) {
                const float* p = a_ + (arow0 + r * 8) * ROWF + tig * 8;
                aw[r][0] = *(const float4*)p;
                aw[r][1] = *(const float4*)(p + 4);
            }
#pragma unroll
            for (int ni = 0; ni < 4; ni++) {
                const float* p = w_ + (brow0 + ni * 8) * ROWF + tig * 8;
                bw[ni][0] = *(const float4*)p;
                bw[ni][1] = *(const float4*)(p + 4);
            }
#pragma unroll
            for (int ks = 0; ks < 4; ++ks) {
#pragma unroll
                for (int ni = 0; ni < 4; ++ni) {
                    uint32_t b0 = __float_as_uint(((const float*)&bw[ni][0])[2 * ks]);
                    uint32_t b1 = __float_as_uint(((const float*)&bw[ni][0])[2 * ks + 1]);
#pragma unroll
                    for (int mi = 0; mi < 2; ++mi) {
                        uint32_t a0 = __float_as_uint(((const float*)&aw[mi * 2][0])[2 * ks]);
                        uint32_t a1 = __float_as_uint(((const float*)&aw[mi * 2 + 1][0])[2 * ks]);
                        uint32_t a2 = __float_as_uint(((const float*)&aw[mi * 2][0])[2 * ks + 1]);
                        uint32_t a3 =
                            __float_as_uint(((const float*)&aw[mi * 2 + 1][0])[2 * ks + 1]);
                        asm volatile(
                            "mma.sync.aligned.m16n8k8.row.col.f32.tf32.tf32.f32 "
                            "{%0,%1,%2,%3},{%4,%5,%6,%7},{%8,%9},{%0,%1,%2,%3};\n"
                            : "+f"(acc[mi][ni][0]), "+f"(acc[mi][ni][1]),
                              "+f"(acc[mi][ni][2]), "+f"(acc[mi][ni][3])
                            : "r"(a0), "r"(a1), "r"(a2), "r"(a3), "r"(b0), "r"(b1));
                    }
                }
            }
            __syncthreads();
        }

        // A rows for mi: mi=0 -> arow0, arow0+8 ; mi=1 -> arow0+16, arow0+24
#pragma unroll
        for (int mi = 0; mi < 2; mi++) {
            int row0 = bm * BM + arow0 + mi * 16;
#pragma unroll
            for (int ni = 0; ni < 4; ni++) {
                int col = bn * BN + wn * 32 + ni * 8 + tig * 2;
                float2 bv = *(const float2*)(bias + col);
                float2 v0, v1;
                v0.x = acc[mi][ni][0] + bv.x;
                v0.y = acc[mi][ni][1] + bv.y;
                v1.x = acc[mi][ni][2] + bv.x;
                v1.y = acc[mi][ni][3] + bv.y;
                float2* p0 = (float2*)(C + (size_t)row0 * N + col);
                float2* p1 = (float2*)(C + (size_t)(row0 + 8) * N + col);
                if (FLAGS & F_RES) {
                    float2 r0v = *p0, r1v = *p1;
                    v0.x += r0v.x;
                    v0.y += r0v.y;
                    v1.x += r1v.x;
                    v1.y += r1v.y;
                }
                if (FLAGS & F_RELU) {
                    v0.x = fmaxf(v0.x, 0.f);
                    v0.y = fmaxf(v0.y, 0.f);
                    v1.x = fmaxf(v1.x, 0.f);
                    v1.y = fmaxf(v1.y, 0.f);
                }
                if (FLAGS & F_RND) {
                    v0.x = rnaf(v0.x);
                    v0.y = rnaf(v0.y);
                    v1.x = rnaf(v1.x);
                    v1.y = rnaf(v1.y);
                }
                *p0 = v0;
                *p1 = v1;
            }
        }
    }
}

// ---------------------------------------------------------------------------
// Persistent kernel: whole recurrence in one launch (1 graph node).
// ---------------------------------------------------------------------------
__global__ __launch_bounds__(GTHR, 2) void persistent_kernel(
    const int* __restrict__ a_seq, const int* __restrict__ b_seq,
    const float* __restrict__ bit_emb, const float* __restrict__ start_state,
    const float* __restrict__ ln1_g, const float* __restrict__ ln1_b,
    const float* __restrict__ qkv_w, const float* __restrict__ qkv_b,
    const float* __restrict__ out_w, const float* __restrict__ out_b,
    const float* __restrict__ ln2_g, const float* __restrict__ ln2_b,
    const float* __restrict__ ff1_w, const float* __restrict__ ff1_b,
    const float* __restrict__ ff2_w, const float* __restrict__ ff2_b,
    const float* __restrict__ head_w, const float* __restrict__ head_b, float* __restrict__ out) {
    extern __shared__ float sm[];

    prep_phase(qkv_w, out_w, ff1_w, ff2_w, ln1_g, ln1_b, ln2_g, ln2_b, qkv_b, out_b, ff1_b,
               ff2_b, bit_emb, start_state, head_w);
    grid_bar();
    emb0_phase(a_seq, b_seq);
    grid_bar();

    for (int t = 0; t < NS; ++t) {
        for (int l = 0; l < NDEPTH; ++l) {
            ln_phase(g_x, g_y, g_ln1g + l * ND, g_ln1b + l * ND);
            grid_bar();
            gemm_phase<F_RND>(g_y, g_wv + (size_t)l * ND * ND, g_bv + l * ND, g_v, ND, ND, sm);
            grid_bar();
            gemm_phase<F_RES>(g_v, g_wo + (size_t)l * ND * ND, g_bo + l * ND, g_x, ND, ND, sm);
            grid_bar();
            ln_phase(g_x, g_y, g_ln2g + l * ND, g_ln2b + l * ND);
            grid_bar();
            gemm_phase<F_RELU | F_RND>(g_y, g_w1 + (size_t)l * 4 * ND * ND, g_b1 + l * 4 * ND,
                                       g_h, ND, 4 * ND, sm);
            grid_bar();
            gemm_phase<F_RES>(g_h, g_w2 + (size_t)l * 4 * ND * ND, g_b2 + l * ND, g_x, 4 * ND,
                              ND, sm);
            grid_bar();
        }
        heademb_phase(head_b, out, a_seq, b_seq, t);
        grid_bar();
    }
}

// ---------------------------------------------------------------------------
extern "C" void kernel_launch(void* const* d_in, const int* in_sizes, int n_in,
                              void* d_out, int out_size) {
    const int* a_seq = (const int*)d_in[0];
    const int* b_seq = (const int*)d_in[1];
    const float* bit_emb = (const float*)d_in[2];
    const float* start_state = (const float*)d_in[3];
    const float* ln1_g = (const float*)d_in[4];
    const float* ln1_b = (const float*)d_in[5];
    const float* qkv_w = (const float*)d_in[6];
    const float* qkv_b = (const float*)d_in[7];
    const float* out_w = (const float*)d_in[8];
    const float* out_b = (const float*)d_in[9];
    const float* ln2_g = (const float*)d_in[10];
    const float* ln2_b = (const float*)d_in[11];
    const float* ff1_w = (const float*)d_in[12];
    const float* ff1_b = (const float*)d_in[13];
    const float* ff2_w = (const float*)d_in[14];
    const float* ff2_b = (const float*)d_in[15];
    const float* head_w = (const float*)d_in[16];
    const float* head_b = (const float*)d_in[17];
    float* out = (float*)d_out;

    const int smem = SMEM_F * (int)sizeof(float);
    static int configured = 0;
    if (!configured) {
        cudaFuncSetAttribute(persistent_kernel, cudaFuncAttributeMaxDynamicSharedMemorySize, smem);
        configured = 1;
    }

    persistent_kernel<<<GBLK, GTHR, smem>>>(a_seq, b_seq, bit_emb, start_state, ln1_g, ln1_b,
                                            qkv_w, qkv_b, out_w, out_b, ln2_g, ln2_b, ff1_w,
                                            ff1_b, ff2_w, ff2_b, head_w, head_b, out);
}

// round 6
// speedup vs baseline: 1.3747x; 1.3747x over previous
#include <cuda_runtime.h>
#include <cstdint>

#define NB 4096
#define NS 64
#define ND 512
#define NDEPTH 4
#define LN_EPS 1e-5f

#define BM 128
#define BN 64
#define BK 32
#define WLD 72  // 64 + 8 pad floats per W smem row (conflict-free B LDS)

#define GBLK 256
#define GTHR 256

#define A_ST_F (BM * BK)               // 4096 floats per A stage
#define W_ST_F (BK * WLD)              // 2304 floats per W stage
#define W_OFF_F (3 * A_ST_F)           // 12288
#define SMEM_F (W_OFF_F + 3 * W_ST_F)  // 19200 floats = 76800 B

#define F_RND 1
#define F_RELU 2
#define F_RES 4

// Activation scratch
static __device__ __align__(128) float g_x[NB * ND];
static __device__ __align__(128) float g_y[NB * ND];
static __device__ __align__(128) float g_h[NB * 4 * ND];
// Prepared weights (RNA tf32-rounded, original [K,N] layout)
static __device__ __align__(128) float g_wc[NDEPTH * ND * ND];       // Wv @ Wo combined
static __device__ __align__(128) float g_w1r[NDEPTH * ND * 4 * ND];
static __device__ __align__(128) float g_w2r[NDEPTH * 4 * ND * ND];
static __device__ float g_bc[NDEPTH * ND];  // bv @ Wo + bo

static __device__ unsigned g_bar = 0;
static __device__ volatile unsigned g_epoch = 0;

__device__ __forceinline__ void grid_bar() {
    __threadfence();
    __syncthreads();
    if (threadIdx.x == 0) {
        unsigned e = g_epoch;
        if (atomicAdd(&g_bar, 1u) == GBLK - 1) {
            g_bar = 0;
            __threadfence();
            g_epoch = e + 1;
        } else {
            while (g_epoch == e) __nanosleep(32);
            __threadfence();
        }
    }
    __syncthreads();
}

__device__ __forceinline__ float warp_sum(float v) {
#pragma unroll
    for (int o = 16; o > 0; o >>= 1) v += __shfl_xor_sync(0xffffffffu, v, o);
    return v;
}

__device__ __forceinline__ float rnaf(float f) {
    uint32_t r;
    asm("cvt.rna.tf32.f32 %0, %1;" : "=r"(r) : "f"(f));
    return __uint_as_float(r);
}

__device__ __forceinline__ void cpasync16(void* smem, const void* gmem) {
    uint32_t sa = (uint32_t)__cvta_generic_to_shared(smem);
    asm volatile("cp.async.cg.shared.global [%0], [%1], 16;\n" ::"r"(sa), "l"(gmem));
}

// ---------------------------------------------------------------------------
// One-time prep: Wc = rna(Wv @ Wo), bc = bv @ Wo + bo, rna copies of ff1/ff2.
// ---------------------------------------------------------------------------
__device__ void prep_phase(const float* __restrict__ qkv_w, const float* __restrict__ qkv_b,
                           const float* __restrict__ out_w, const float* __restrict__ out_b,
                           const float* __restrict__ ff1_w, const float* __restrict__ ff2_w) {
    const int gtid = blockIdx.x * GTHR + threadIdx.x;
    const int stride = GBLK * GTHR;
    // Wc[l][k][n] = rna( sum_j qkv_w[l][k][2D+j] * out_w[l][j][n] )
    for (int i = gtid; i < NDEPTH * ND * ND; i += stride) {
        int n = i & (ND - 1), k = (i >> 9) & (ND - 1), l = i >> 18;
        const float* wv = qkv_w + ((size_t)l * ND + k) * (3 * ND) + 2 * ND;
        const float* wo = out_w + (size_t)l * ND * ND + n;
        float s = 0.f;
#pragma unroll 4
        for (int j = 0; j < ND; j++) s += wv[j] * wo[(size_t)j * ND];
        g_wc[i] = rnaf(s);
    }
    // bc[l][n] = sum_j bv[j] * Wo[j][n] + bo[n]
    for (int i = gtid; i < NDEPTH * ND; i += stride) {
        int n = i & (ND - 1), l = i >> 9;
        const float* bv = qkv_b + l * 3 * ND + 2 * ND;
        const float* wo = out_w + (size_t)l * ND * ND + n;
        float s = out_b[l * ND + n];
#pragma unroll 4
        for (int j = 0; j < ND; j++) s += bv[j] * wo[(size_t)j * ND];
        g_bc[i] = s;
    }
    for (int i = gtid; i < NDEPTH * ND * 4 * ND; i += stride) g_w1r[i] = rnaf(ff1_w[i]);
    for (int i = gtid; i < NDEPTH * 4 * ND * ND; i += stride) g_w2r[i] = rnaf(ff2_w[i]);
}

// ---------------------------------------------------------------------------
// Elementwise phases (warp per row)
// ---------------------------------------------------------------------------
__device__ void emb0_phase(const int* __restrict__ a_seq, const int* __restrict__ b_seq,
                           const float* __restrict__ emb, const float* __restrict__ start) {
    int gw = blockIdx.x * 8 + (threadIdx.x >> 5);
    int lane = threadIdx.x & 31;
    for (int row = gw; row < NB; row += GBLK * 8) {
        int a = a_seq[row * NS];
        int b = b_seq[row * NS];
        const float4* ea = (const float4*)(emb + (size_t)a * ND);
        const float4* eb = (const float4*)(emb + (size_t)b * ND);
        const float4* ss = (const float4*)start;
        float4* xr = (float4*)(g_x + (size_t)row * ND);
#pragma unroll
        for (int j = 0; j < 4; j++) {
            int c = lane + 32 * j;
            float4 va = ea[c], vb = eb[c], vs = ss[c];
            float4 o;
            o.x = va.x + vb.x + vs.x;
            o.y = va.y + vb.y + vs.y;
            o.z = va.z + vb.z + vs.z;
            o.w = va.w + vb.w + vs.w;
            xr[c] = o;
        }
    }
}

__device__ void ln_phase(const float* __restrict__ x, float* __restrict__ y,
                         const float* __restrict__ g, const float* __restrict__ b) {
    int gw = blockIdx.x * 8 + (threadIdx.x >> 5);
    int lane = threadIdx.x & 31;
    for (int row = gw; row < NB; row += GBLK * 8) {
        const float4* xr = (const float4*)(x + (size_t)row * ND);
        float4 v[4];
        float s = 0.f;
#pragma unroll
        for (int j = 0; j < 4; j++) {
            v[j] = xr[lane + 32 * j];
            s += v[j].x + v[j].y + v[j].z + v[j].w;
        }
        s = warp_sum(s);
        float mean = s * (1.0f / ND);
        float q = 0.f;
#pragma unroll
        for (int j = 0; j < 4; j++) {
            float cx = v[j].x - mean, cy = v[j].y - mean;
            float cz = v[j].z - mean, cw = v[j].w - mean;
            q += cx * cx + cy * cy + cz * cz + cw * cw;
        }
        q = warp_sum(q);
        float r = rsqrtf(q * (1.0f / ND) + LN_EPS);
        float4* yr = (float4*)(y + (size_t)row * ND);
#pragma unroll
        for (int j = 0; j < 4; j++) {
            int c = lane + 32 * j;
            float4 gg = ((const float4*)g)[c];
            float4 bb = ((const float4*)b)[c];
            float4 o;
            o.x = rnaf((v[j].x - mean) * r * gg.x + bb.x);
            o.y = rnaf((v[j].y - mean) * r * gg.y + bb.y);
            o.z = rnaf((v[j].z - mean) * r * gg.z + bb.z);
            o.w = rnaf((v[j].w - mean) * r * gg.w + bb.w);
            yr[c] = o;
        }
    }
}

__device__ void heademb_phase(const float* __restrict__ hw, const float* __restrict__ hb,
                              float* __restrict__ out, const int* __restrict__ a_seq,
                              const int* __restrict__ b_seq, const float* __restrict__ emb,
                              int t) {
    int gw = blockIdx.x * 8 + (threadIdx.x >> 5);
    int lane = threadIdx.x & 31;
    for (int row = gw; row < NB; row += GBLK * 8) {
        float4* xr = (float4*)(g_x + (size_t)row * ND);
        float4 v[4];
        float s0 = 0.f, s1 = 0.f;
#pragma unroll
        for (int j = 0; j < 4; j++) {
            int c = lane + 32 * j;
            v[j] = xr[c];
#pragma unroll
            for (int u = 0; u < 4; u++) {
                float xv = (&v[j].x)[u];
                float2 w = ((const float2*)hw)[c * 4 + u];
                s0 += xv * w.x;
                s1 += xv * w.y;
            }
        }
        s0 = warp_sum(s0);
        s1 = warp_sum(s1);
        if (lane == 0) {
            out[(size_t)row * NS * 2 + t * 2 + 0] = s0 + hb[0];
            out[(size_t)row * NS * 2 + t * 2 + 1] = s1 + hb[1];
        }
        if (t + 1 < NS) {
            int a = a_seq[row * NS + t + 1];
            int b = b_seq[row * NS + t + 1];
            const float4* ea = (const float4*)(emb + (size_t)a * ND);
            const float4* eb = (const float4*)(emb + (size_t)b * ND);
#pragma unroll
            for (int j = 0; j < 4; j++) {
                int c = lane + 32 * j;
                float4 va = ea[c], vb = eb[c];
                float4 o = v[j];
                o.x += va.x + vb.x;
                o.y += va.y + vb.y;
                o.z += va.z + vb.z;
                o.w += va.w + vb.w;
                xr[c] = o;
            }
        }
    }
}

// ---------------------------------------------------------------------------
// TF32 GEMM (R3-proven inner loop), 3-stage cp.async, 1 sync per ktile.
// C = epi(A[M,K] @ W[K,N] + bias); W pre-rounded, raw bits fed to HMMA.
// 128x64 tiles, 8 warps 4x2, warp tile 32x32, mma m16n8k8.
// ---------------------------------------------------------------------------
template <int FLAGS>
__device__ void gemm_phase(const float* __restrict__ A, const float* __restrict__ W,
                           const float* __restrict__ bias, float* __restrict__ C, int K, int N,
                           int ldw, float* sm) {
    float* sA = sm;            // 3 stages of BM*BK
    float* sW = sm + W_OFF_F;  // 3 stages of BK*WLD

    const int tid = threadIdx.x;
    const int warp = tid >> 5, lane = tid & 31;
    const int wm = warp >> 1, wn = warp & 1;  // 4 x 2 warp grid
    const int gid = lane >> 2, tig = lane & 3;

    const int ar0 = wm * 32 + gid;
    const int nb = wn * 32 + gid;
    const int bbase = tig * WLD + nb;

    const int ntN = N / BN;
    const int ntiles = (NB / BM) * ntN;
    const int KT = K / BK;

    for (int tile = blockIdx.x; tile < ntiles; tile += GBLK) {
        const int bm = tile / ntN, bn = tile % ntN;
        const float* Ag = A + (size_t)bm * BM * K;
        const float* Wg = W + (size_t)bn * BN;

        float acc[2][4][4];
#pragma unroll
        for (int i = 0; i < 2; i++)
#pragma unroll
            for (int j = 0; j < 4; j++)
#pragma unroll
                for (int k = 0; k < 4; k++) acc[i][j][k] = 0.f;

        auto load_tiles = [&](int kt, int st) {
            float* dA = sA + st * A_ST_F;
            const float* srcA = Ag + kt * BK;
#pragma unroll
            for (int i = 0; i < 4; i++) {
                int c = tid + i * 256;
                int row = c >> 3, cc = c & 7;
                int sc = cc ^ (row & 7);
                cpasync16(dA + row * BK + sc * 4, srcA + (size_t)row * K + cc * 4);
            }
            float* dW = sW + st * W_ST_F;
            const float* srcW = Wg + (size_t)kt * BK * ldw;
#pragma unroll
            for (int i = 0; i < 2; i++) {
                int c = tid + i * 256;
                int row = c >> 4, cc = c & 15;
                cpasync16(dW + row * WLD + cc * 4, srcW + (size_t)row * ldw + cc * 4);
            }
            asm volatile("cp.async.commit_group;\n");
        };

        load_tiles(0, 0);
        load_tiles(1, 1);

        int st = 0;
        for (int kt = 0; kt < KT; ++kt, st = (st == 2) ? 0 : st + 1) {
            if (kt == KT - 1) {
                asm volatile("cp.async.wait_group 0;\n");
            } else {
                asm volatile("cp.async.wait_group 1;\n");
            }
            __syncthreads();
            if (kt + 2 < KT) {
                int st2 = st + 2;
                if (st2 >= 3) st2 -= 3;
                load_tiles(kt + 2, st2);
            }
            const float* a_ = sA + st * A_ST_F;
            const float* w_ = sW + st * W_ST_F;
#pragma unroll
            for (int ks = 0; ks < 4; ++ks) {
                const int x0 = ((2 * ks) ^ gid) * 4 + tig;
                const int x1 = ((2 * ks + 1) ^ gid) * 4 + tig;
                uint32_t af[2][4];
#pragma unroll
                for (int mi = 0; mi < 2; ++mi) {
                    const int r0 = (ar0 + mi * 16) * BK;
                    const int r1 = r0 + 8 * BK;
                    af[mi][0] = __float_as_uint(a_[r0 + x0]);
                    af[mi][1] = __float_as_uint(a_[r1 + x0]);
                    af[mi][2] = __float_as_uint(a_[r0 + x1]);
                    af[mi][3] = __float_as_uint(a_[r1 + x1]);
                }
                const int bk = bbase + ks * 8 * WLD;
#pragma unroll
                for (int ni = 0; ni < 4; ++ni) {
                    uint32_t b0 = __float_as_uint(w_[bk + ni * 8]);
                    uint32_t b1 = __float_as_uint(w_[bk + 4 * WLD + ni * 8]);
#pragma unroll
                    for (int mi = 0; mi < 2; ++mi) {
                        asm volatile(
                            "mma.sync.aligned.m16n8k8.row.col.f32.tf32.tf32.f32 "
                            "{%0,%1,%2,%3},{%4,%5,%6,%7},{%8,%9},{%0,%1,%2,%3};\n"
                            : "+f"(acc[mi][ni][0]), "+f"(acc[mi][ni][1]),
                              "+f"(acc[mi][ni][2]), "+f"(acc[mi][ni][3])
                            : "r"(af[mi][0]), "r"(af[mi][1]), "r"(af[mi][2]), "r"(af[mi][3]),
                              "r"(b0), "r"(b1));
                    }
                }
            }
        }

#pragma unroll
        for (int mi = 0; mi < 2; mi++) {
            int row0 = bm * BM + wm * 32 + mi * 16 + gid;
#pragma unroll
            for (int ni = 0; ni < 4; ni++) {
                int col = bn * BN + wn * 32 + ni * 8 + tig * 2;
                float2 bv = *(const float2*)(bias + col);
                float2 v0, v1;
                v0.x = acc[mi][ni][0] + bv.x;
                v0.y = acc[mi][ni][1] + bv.y;
                v1.x = acc[mi][ni][2] + bv.x;
                v1.y = acc[mi][ni][3] + bv.y;
                float2* p0 = (float2*)(C + (size_t)row0 * N + col);
                float2* p1 = (float2*)(C + (size_t)(row0 + 8) * N + col);
                if (FLAGS & F_RES) {
                    float2 r0v = *p0, r1v = *p1;
                    v0.x += r0v.x;
                    v0.y += r0v.y;
                    v1.x += r1v.x;
                    v1.y += r1v.y;
                }
                if (FLAGS & F_RELU) {
                    v0.x = fmaxf(v0.x, 0.f);
                    v0.y = fmaxf(v0.y, 0.f);
                    v1.x = fmaxf(v1.x, 0.f);
                    v1.y = fmaxf(v1.y, 0.f);
                }
                if (FLAGS & F_RND) {
                    v0.x = rnaf(v0.x);
                    v0.y = rnaf(v0.y);
                    v1.x = rnaf(v1.x);
                    v1.y = rnaf(v1.y);
                }
                *p0 = v0;
                *p1 = v1;
            }
        }
        __syncthreads();
    }
}

// ---------------------------------------------------------------------------
// Persistent kernel: whole recurrence in one launch (1 graph node).
// ---------------------------------------------------------------------------
__global__ __launch_bounds__(GTHR, 2) void persistent_kernel(
    const int* __restrict__ a_seq, const int* __restrict__ b_seq,
    const float* __restrict__ bit_emb, const float* __restrict__ start_state,
    const float* __restrict__ ln1_g, const float* __restrict__ ln1_b,
    const float* __restrict__ qkv_w, const float* __restrict__ qkv_b,
    const float* __restrict__ out_w, const float* __restrict__ out_b,
    const float* __restrict__ ln2_g, const float* __restrict__ ln2_b,
    const float* __restrict__ ff1_w, const float* __restrict__ ff1_b,
    const float* __restrict__ ff2_w, const float* __restrict__ ff2_b,
    const float* __restrict__ head_w, const float* __restrict__ head_b, float* __restrict__ out) {
    extern __shared__ float sm[];

    prep_phase(qkv_w, qkv_b, out_w, out_b, ff1_w, ff2_w);
    emb0_phase(a_seq, b_seq, bit_emb, start_state);
    grid_bar();

    for (int t = 0; t < NS; ++t) {
        for (int l = 0; l < NDEPTH; ++l) {
            // y = rna(LN1(x))
            ln_phase(g_x, g_y, ln1_g + l * ND, ln1_b + l * ND);
            grid_bar();
            // x += y @ Wc + bc   (fused v/out projection)
            gemm_phase<F_RES>(g_y, g_wc + (size_t)l * ND * ND, g_bc + l * ND, g_x, ND, ND, ND,
                              sm);
            grid_bar();
            // y = rna(LN2(x))
            ln_phase(g_x, g_y, ln2_g + l * ND, ln2_b + l * ND);
            grid_bar();
            // h = rna(relu(y @ W1 + b1))
            gemm_phase<F_RELU | F_RND>(g_y, g_w1r + (size_t)l * ND * 4 * ND,
                                       ff1_b + (size_t)l * 4 * ND, g_h, ND, 4 * ND, 4 * ND, sm);
            grid_bar();
            // x += h @ W2 + b2
            gemm_phase<F_RES>(g_h, g_w2r + (size_t)l * 4 * ND * ND, ff2_b + (size_t)l * ND, g_x,
                              4 * ND, ND, ND, sm);
            grid_bar();
        }
        heademb_phase(head_w, head_b, out, a_seq, b_seq, bit_emb, t);
        grid_bar();
    }
}

// ---------------------------------------------------------------------------
extern "C" void kernel_launch(void* const* d_in, const int* in_sizes, int n_in,
                              void* d_out, int out_size) {
    const int* a_seq = (const int*)d_in[0];
    const int* b_seq = (const int*)d_in[1];
    const float* bit_emb = (const float*)d_in[2];
    const float* start_state = (const float*)d_in[3];
    const float* ln1_g = (const float*)d_in[4];
    const float* ln1_b = (const float*)d_in[5];
    const float* qkv_w = (const float*)d_in[6];
    const float* qkv_b = (const float*)d_in[7];
    const float* out_w = (const float*)d_in[8];
    const float* out_b = (const float*)d_in[9];
    const float* ln2_g = (const float*)d_in[10];
    const float* ln2_b = (const float*)d_in[11];
    const float* ff1_w = (const float*)d_in[12];
    const float* ff1_b = (const float*)d_in[13];
    const float* ff2_w = (const float*)d_in[14];
    const float* ff2_b = (const float*)d_in[15];
    const float* head_w = (const float*)d_in[16];
    const float* head_b = (const float*)d_in[17];
    float* out = (float*)d_out;

    const int smem = SMEM_F * (int)sizeof(float);
    static int configured = 0;
    if (!configured) {
        cudaFuncSetAttribute(persistent_kernel, cudaFuncAttributeMaxDynamicSharedMemorySize, smem);
        configured = 1;
    }

    persistent_kernel<<<GBLK, GTHR, smem>>>(a_seq, b_seq, bit_emb, start_state, ln1_g, ln1_b,
                                            qkv_w, qkv_b, out_w, out_b, ln2_g, ln2_b, ff1_w,
                                            ff1_b, ff2_w, ff2_b, head_w, head_b, out);
}

// round 7
// speedup vs baseline: 1.5884x; 1.1554x over previous
#include <cuda_runtime.h>
#include <cstdint>

#define NB 4096
#define NS 64
#define ND 512
#define NDEPTH 4
#define LN_EPS 1e-5f

#define BM 128
#define BN 128
#define BK 32
#define WLD 136  // 128 + 8 pad floats per W smem row (conflict-free B LDS)

#define GBLK 256
#define GTHR 256

#define A_ST_F (BM * BK)               // 4096 floats per A stage
#define W_ST_F (BK * WLD)              // 4352 floats per W stage
#define W_OFF_F (3 * A_ST_F)           // 12288
#define SMEM_F (W_OFF_F + 3 * W_ST_F)  // 25344 floats = 101376 B

#define F_RAW 0
#define F_EPI 1  // bias + relu + rna (ff1)

// Activation scratch
static __device__ __align__(128) float g_x[NB * ND];
static __device__ __align__(128) float g_y[NB * ND];
static __device__ __align__(128) float g_h[NB * 4 * ND];
static __device__ __align__(128) float g_p0[NB * ND];  // split-K partial 0
static __device__ __align__(128) float g_p1[NB * ND];  // split-K partial 1
// Prepared weights (RNA tf32-rounded, [K,N] layout)
static __device__ __align__(128) float g_wc[NDEPTH * ND * ND];  // Wv @ Wo
static __device__ __align__(128) float g_w1r[NDEPTH * ND * 4 * ND];
static __device__ __align__(128) float g_w2r[NDEPTH * 4 * ND * ND];
static __device__ float g_bc[NDEPTH * ND];  // bv @ Wo + bo

static __device__ unsigned g_bar = 0;
static __device__ volatile unsigned g_epoch = 0;

__device__ __forceinline__ void grid_bar() {
    __threadfence();
    __syncthreads();
    if (threadIdx.x == 0) {
        unsigned e = g_epoch;
        if (atomicAdd(&g_bar, 1u) == GBLK - 1) {
            g_bar = 0;
            __threadfence();
            g_epoch = e + 1;
        } else {
            while (g_epoch == e) __nanosleep(32);
            __threadfence();
        }
    }
    __syncthreads();
}

__device__ __forceinline__ float warp_sum(float v) {
#pragma unroll
    for (int o = 16; o > 0; o >>= 1) v += __shfl_xor_sync(0xffffffffu, v, o);
    return v;
}

__device__ __forceinline__ float rnaf(float f) {
    uint32_t r;
    asm("cvt.rna.tf32.f32 %0, %1;" : "=r"(r) : "f"(f));
    return __uint_as_float(r);
}

__device__ __forceinline__ void cpasync16(void* smem, const void* gmem) {
    uint32_t sa = (uint32_t)__cvta_generic_to_shared(smem);
    asm volatile("cp.async.cg.shared.global [%0], [%1], 16;\n" ::"r"(sa), "l"(gmem));
}

// ---------------------------------------------------------------------------
// One-time prep: Wc = rna(Wv @ Wo), bc = bv @ Wo + bo, rna copies of ff1/ff2.
// ---------------------------------------------------------------------------
__device__ void prep_phase(const float* __restrict__ qkv_w, const float* __restrict__ qkv_b,
                           const float* __restrict__ out_w, const float* __restrict__ out_b,
                           const float* __restrict__ ff1_w, const float* __restrict__ ff2_w) {
    const int gtid = blockIdx.x * GTHR + threadIdx.x;
    const int stride = GBLK * GTHR;
    for (int i = gtid; i < NDEPTH * ND * ND; i += stride) {
        int n = i & (ND - 1), k = (i >> 9) & (ND - 1), l = i >> 18;
        const float* wv = qkv_w + ((size_t)l * ND + k) * (3 * ND) + 2 * ND;
        const float* wo = out_w + (size_t)l * ND * ND + n;
        float s = 0.f;
#pragma unroll 4
        for (int j = 0; j < ND; j++) s += wv[j] * wo[(size_t)j * ND];
        g_wc[i] = rnaf(s);
    }
    for (int i = gtid; i < NDEPTH * ND; i += stride) {
        int n = i & (ND - 1), l = i >> 9;
        const float* bv = qkv_b + l * 3 * ND + 2 * ND;
        const float* wo = out_w + (size_t)l * ND * ND + n;
        float s = out_b[l * ND + n];
#pragma unroll 4
        for (int j = 0; j < ND; j++) s += bv[j] * wo[(size_t)j * ND];
        g_bc[i] = s;
    }
    for (int i = gtid; i < NDEPTH * ND * 4 * ND; i += stride) g_w1r[i] = rnaf(ff1_w[i]);
    for (int i = gtid; i < NDEPTH * 4 * ND * ND; i += stride) g_w2r[i] = rnaf(ff2_w[i]);
}

// ---------------------------------------------------------------------------
// Elementwise phases (warp per row)
// ---------------------------------------------------------------------------
__device__ void emb0_phase(const int* __restrict__ a_seq, const int* __restrict__ b_seq,
                           const float* __restrict__ emb, const float* __restrict__ start) {
    int gw = blockIdx.x * 8 + (threadIdx.x >> 5);
    int lane = threadIdx.x & 31;
    for (int row = gw; row < NB; row += GBLK * 8) {
        int a = a_seq[row * NS];
        int b = b_seq[row * NS];
        const float4* ea = (const float4*)(emb + (size_t)a * ND);
        const float4* eb = (const float4*)(emb + (size_t)b * ND);
        const float4* ss = (const float4*)start;
        float4* xr = (float4*)(g_x + (size_t)row * ND);
#pragma unroll
        for (int j = 0; j < 4; j++) {
            int c = lane + 32 * j;
            float4 va = ea[c], vb = eb[c], vs = ss[c];
            float4 o;
            o.x = va.x + vb.x + vs.x;
            o.y = va.y + vb.y + vs.y;
            o.z = va.z + vb.z + vs.z;
            o.w = va.w + vb.w + vs.w;
            xr[c] = o;
        }
    }
}

// LN with optional fused split-K reduction: x = x + p0 + p1 + addb, then y = rna(LN(x)).
template <bool FUSE>
__device__ void ln_phase(float* __restrict__ x, float* __restrict__ y,
                         const float* __restrict__ p0, const float* __restrict__ p1,
                         const float* __restrict__ addb, const float* __restrict__ g,
                         const float* __restrict__ b) {
    int gw = blockIdx.x * 8 + (threadIdx.x >> 5);
    int lane = threadIdx.x & 31;
    for (int row = gw; row < NB; row += GBLK * 8) {
        float4* xr = (float4*)(x + (size_t)row * ND);
        float4 v[4];
        float s = 0.f;
#pragma unroll
        for (int j = 0; j < 4; j++) {
            int c = lane + 32 * j;
            v[j] = xr[c];
            if (FUSE) {
                float4 a0 = ((const float4*)(p0 + (size_t)row * ND))[c];
                float4 a1 = ((const float4*)(p1 + (size_t)row * ND))[c];
                float4 ab = ((const float4*)addb)[c];
                v[j].x += a0.x + a1.x + ab.x;
                v[j].y += a0.y + a1.y + ab.y;
                v[j].z += a0.z + a1.z + ab.z;
                v[j].w += a0.w + a1.w + ab.w;
                xr[c] = v[j];
            }
            s += v[j].x + v[j].y + v[j].z + v[j].w;
        }
        s = warp_sum(s);
        float mean = s * (1.0f / ND);
        float q = 0.f;
#pragma unroll
        for (int j = 0; j < 4; j++) {
            float cx = v[j].x - mean, cy = v[j].y - mean;
            float cz = v[j].z - mean, cw = v[j].w - mean;
            q += cx * cx + cy * cy + cz * cz + cw * cw;
        }
        q = warp_sum(q);
        float r = rsqrtf(q * (1.0f / ND) + LN_EPS);
        float4* yr = (float4*)(y + (size_t)row * ND);
#pragma unroll
        for (int j = 0; j < 4; j++) {
            int c = lane + 32 * j;
            float4 gg = ((const float4*)g)[c];
            float4 bb = ((const float4*)b)[c];
            float4 o;
            o.x = rnaf((v[j].x - mean) * r * gg.x + bb.x);
            o.y = rnaf((v[j].y - mean) * r * gg.y + bb.y);
            o.z = rnaf((v[j].z - mean) * r * gg.z + bb.z);
            o.w = rnaf((v[j].w - mean) * r * gg.w + bb.w);
            yr[c] = o;
        }
    }
}

// Head with fused ff2 reduction: x += p0+p1+b2; logits; x += emb(t+1).
__device__ void heademb_phase(const float* __restrict__ p0, const float* __restrict__ p1,
                              const float* __restrict__ addb, const float* __restrict__ hw,
                              const float* __restrict__ hb, float* __restrict__ out,
                              const int* __restrict__ a_seq, const int* __restrict__ b_seq,
                              const float* __restrict__ emb, int t) {
    int gw = blockIdx.x * 8 + (threadIdx.x >> 5);
    int lane = threadIdx.x & 31;
    for (int row = gw; row < NB; row += GBLK * 8) {
        float4* xr = (float4*)(g_x + (size_t)row * ND);
        float4 v[4];
        float s0 = 0.f, s1 = 0.f;
#pragma unroll
        for (int j = 0; j < 4; j++) {
            int c = lane + 32 * j;
            v[j] = xr[c];
            float4 a0 = ((const float4*)(p0 + (size_t)row * ND))[c];
            float4 a1 = ((const float4*)(p1 + (size_t)row * ND))[c];
            float4 ab = ((const float4*)addb)[c];
            v[j].x += a0.x + a1.x + ab.x;
            v[j].y += a0.y + a1.y + ab.y;
            v[j].z += a0.z + a1.z + ab.z;
            v[j].w += a0.w + a1.w + ab.w;
#pragma unroll
            for (int u = 0; u < 4; u++) {
                float xv = (&v[j].x)[u];
                float2 w = ((const float2*)hw)[c * 4 + u];
                s0 += xv * w.x;
                s1 += xv * w.y;
            }
        }
        s0 = warp_sum(s0);
        s1 = warp_sum(s1);
        if (lane == 0) {
            out[(size_t)row * NS * 2 + t * 2 + 0] = s0 + hb[0];
            out[(size_t)row * NS * 2 + t * 2 + 1] = s1 + hb[1];
        }
        if (t + 1 < NS) {
            int a = a_seq[row * NS + t + 1];
            int b = b_seq[row * NS + t + 1];
            const float4* ea = (const float4*)(emb + (size_t)a * ND);
            const float4* eb = (const float4*)(emb + (size_t)b * ND);
#pragma unroll
            for (int j = 0; j < 4; j++) {
                v[j].x += ea[lane + 32 * j].x + eb[lane + 32 * j].x;
                v[j].y += ea[lane + 32 * j].y + eb[lane + 32 * j].y;
                v[j].z += ea[lane + 32 * j].z + eb[lane + 32 * j].z;
                v[j].w += ea[lane + 32 * j].w + eb[lane + 32 * j].w;
                xr[lane + 32 * j] = v[j];
            }
        } else {
#pragma unroll
            for (int j = 0; j < 4; j++) xr[lane + 32 * j] = v[j];
        }
    }
}

// ---------------------------------------------------------------------------
// TF32 GEMM: block tile 128x128, 8 warps 4x2, warp tile 32x64, 3-stage cp.async.
// Optional split-K (nsplit jobs along K, partials to C0/C1 raw).
// FLAGS==F_EPI: C0 = rna(relu(acc + bias)).
// ---------------------------------------------------------------------------
template <int FLAGS>
__device__ void gemm_phase(const float* __restrict__ A, int Ktot, const float* __restrict__ W,
                           int ldw, const float* __restrict__ bias, float* __restrict__ C0,
                           float* __restrict__ C1, int N, int KT, int nsplit, float* sm) {
    float* sA = sm;
    float* sW = sm + W_OFF_F;

    const int tid = threadIdx.x;
    const int warp = tid >> 5, lane = tid & 31;
    const int wm = warp >> 1, wn = warp & 1;  // 4 x 2 warp grid
    const int gid = lane >> 2, tig = lane & 3;

    const int ar0 = wm * 32 + gid;
    const int bbase = tig * WLD + wn * 64 + gid;

    const int nT = N / BN;
    const int njobs = (NB / BM) * nT * nsplit;

    for (int job = blockIdx.x; job < njobs; job += GBLK) {
        const int split = job / ((NB / BM) * nT);
        const int rr = job - split * (NB / BM) * nT;
        const int bm = rr / nT, bn = rr % nT;
        const int k0 = split * KT * BK;
        const float* Ag = A + (size_t)bm * BM * Ktot + k0;
        const float* Wg = W + (size_t)k0 * ldw + bn * BN;
        float* C = split ? C1 : C0;

        float acc[2][8][4];
#pragma unroll
        for (int i = 0; i < 2; i++)
#pragma unroll
            for (int j = 0; j < 8; j++)
#pragma unroll
                for (int k = 0; k < 4; k++) acc[i][j][k] = 0.f;

        auto load_tiles = [&](int kt, int st) {
            float* dA = sA + st * A_ST_F;
            const float* srcA = Ag + kt * BK;
#pragma unroll
            for (int i = 0; i < 4; i++) {
                int c = tid + i * 256;
                int row = c >> 3, cc = c & 7;
                int sc = cc ^ (row & 7);
                cpasync16(dA + row * BK + sc * 4, srcA + (size_t)row * Ktot + cc * 4);
            }
            float* dW = sW + st * W_ST_F;
            const float* srcW = Wg + (size_t)kt * BK * ldw;
#pragma unroll
            for (int i = 0; i < 4; i++) {
                int c = tid + i * 256;
                int row = c >> 5, cc = c & 31;
                cpasync16(dW + row * WLD + cc * 4, srcW + (size_t)row * ldw + cc * 4);
            }
            asm volatile("cp.async.commit_group;\n");
        };

        load_tiles(0, 0);
        load_tiles(1, 1);

        int st = 0;
        for (int kt = 0; kt < KT; ++kt, st = (st == 2) ? 0 : st + 1) {
            if (kt == KT - 1) {
                asm volatile("cp.async.wait_group 0;\n");
            } else {
                asm volatile("cp.async.wait_group 1;\n");
            }
            __syncthreads();
            if (kt + 2 < KT) {
                int st2 = st + 2;
                if (st2 >= 3) st2 -= 3;
                load_tiles(kt + 2, st2);
            }
            const float* a_ = sA + st * A_ST_F;
            const float* w_ = sW + st * W_ST_F;
#pragma unroll
            for (int ks = 0; ks < 4; ++ks) {
                const int x0 = ((2 * ks) ^ gid) * 4 + tig;
                const int x1 = ((2 * ks + 1) ^ gid) * 4 + tig;
                uint32_t af[2][4];
#pragma unroll
                for (int mi = 0; mi < 2; ++mi) {
                    const int r0 = (ar0 + mi * 16) * BK;
                    const int r1 = r0 + 8 * BK;
                    af[mi][0] = __float_as_uint(a_[r0 + x0]);
                    af[mi][1] = __float_as_uint(a_[r1 + x0]);
                    af[mi][2] = __float_as_uint(a_[r0 + x1]);
                    af[mi][3] = __float_as_uint(a_[r1 + x1]);
                }
                const int bk = bbase + ks * 8 * WLD;
#pragma unroll
                for (int ni = 0; ni < 8; ++ni) {
                    uint32_t b0 = __float_as_uint(w_[bk + ni * 8]);
                    uint32_t b1 = __float_as_uint(w_[bk + 4 * WLD + ni * 8]);
#pragma unroll
                    for (int mi = 0; mi < 2; ++mi) {
                        asm volatile(
                            "mma.sync.aligned.m16n8k8.row.col.f32.tf32.tf32.f32 "
                            "{%0,%1,%2,%3},{%4,%5,%6,%7},{%8,%9},{%0,%1,%2,%3};\n"
                            : "+f"(acc[mi][ni][0]), "+f"(acc[mi][ni][1]),
                              "+f"(acc[mi][ni][2]), "+f"(acc[mi][ni][3])
                            : "r"(af[mi][0]), "r"(af[mi][1]), "r"(af[mi][2]), "r"(af[mi][3]),
                              "r"(b0), "r"(b1));
                    }
                }
            }
        }

#pragma unroll
        for (int mi = 0; mi < 2; mi++) {
            int row0 = bm * BM + wm * 32 + mi * 16 + gid;
#pragma unroll
            for (int ni = 0; ni < 8; ni++) {
                int col = bn * BN + wn * 64 + ni * 8 + tig * 2;
                float2 v0, v1;
                v0.x = acc[mi][ni][0];
                v0.y = acc[mi][ni][1];
                v1.x = acc[mi][ni][2];
                v1.y = acc[mi][ni][3];
                if (FLAGS == F_EPI) {
                    float2 bv = *(const float2*)(bias + col);
                    v0.x = rnaf(fmaxf(v0.x + bv.x, 0.f));
                    v0.y = rnaf(fmaxf(v0.y + bv.y, 0.f));
                    v1.x = rnaf(fmaxf(v1.x + bv.x, 0.f));
                    v1.y = rnaf(fmaxf(v1.y + bv.y, 0.f));
                }
                *(float2*)(C + (size_t)row0 * N + col) = v0;
                *(float2*)(C + (size_t)(row0 + 8) * N + col) = v1;
            }
        }
        __syncthreads();
    }
}

// ---------------------------------------------------------------------------
// Persistent kernel
// ---------------------------------------------------------------------------
__global__ __launch_bounds__(GTHR, 2) void persistent_kernel(
    const int* __restrict__ a_seq, const int* __restrict__ b_seq,
    const float* __restrict__ bit_emb, const float* __restrict__ start_state,
    const float* __restrict__ ln1_g, const float* __restrict__ ln1_b,
    const float* __restrict__ qkv_w, const float* __restrict__ qkv_b,
    const float* __restrict__ out_w, const float* __restrict__ out_b,
    const float* __restrict__ ln2_g, const float* __restrict__ ln2_b,
    const float* __restrict__ ff1_w, const float* __restrict__ ff1_b,
    const float* __restrict__ ff2_w, const float* __restrict__ ff2_b,
    const float* __restrict__ head_w, const float* __restrict__ head_b, float* __restrict__ out) {
    extern __shared__ float sm[];

    prep_phase(qkv_w, qkv_b, out_w, out_b, ff1_w, ff2_w);
    emb0_phase(a_seq, b_seq, bit_emb, start_state);
    grid_bar();

    for (int t = 0; t < NS; ++t) {
        for (int l = 0; l < NDEPTH; ++l) {
            // LN1: plain at l==0 (x finalized by emb0/head); else fuse ff2 reduce of l-1
            if (l == 0)
                ln_phase<false>(g_x, g_y, nullptr, nullptr, nullptr, ln1_g + l * ND,
                                ln1_b + l * ND);
            else
                ln_phase<true>(g_x, g_y, g_p0, g_p1, ff2_b + (size_t)(l - 1) * ND,
                               ln1_g + l * ND, ln1_b + l * ND);
            grid_bar();
            // Wc GEMM (split-K 2): p0/p1 = y @ Wc
            gemm_phase<F_RAW>(g_y, ND, g_wc + (size_t)l * ND * ND, ND, nullptr, g_p0, g_p1, ND,
                              8, 2, sm);
            grid_bar();
            // LN2 fused: x += p0+p1+bc; y = rna(LN2(x))
            ln_phase<true>(g_x, g_y, g_p0, g_p1, g_bc + l * ND, ln2_g + l * ND, ln2_b + l * ND);
            grid_bar();
            // h = rna(relu(y @ W1 + b1))
            gemm_phase<F_EPI>(g_y, ND, g_w1r + (size_t)l * ND * 4 * ND, 4 * ND,
                              ff1_b + (size_t)l * 4 * ND, g_h, nullptr, 4 * ND, 16, 1, sm);
            grid_bar();
            // ff2 GEMM (split-K 2): p0/p1 = h @ W2
            gemm_phase<F_RAW>(g_h, 4 * ND, g_w2r + (size_t)l * 4 * ND * ND, ND, nullptr, g_p0,
                              g_p1, ND, 32, 2, sm);
            grid_bar();
        }
        // head fused with ff2 reduce of layer 3, then x += emb(t+1)
        heademb_phase(g_p0, g_p1, ff2_b + (size_t)(NDEPTH - 1) * ND, head_w, head_b, out, a_seq,
                      b_seq, bit_emb, t);
        grid_bar();
    }
}

// ---------------------------------------------------------------------------
extern "C" void kernel_launch(void* const* d_in, const int* in_sizes, int n_in,
                              void* d_out, int out_size) {
    const int* a_seq = (const int*)d_in[0];
    const int* b_seq = (const int*)d_in[1];
    const float* bit_emb = (const float*)d_in[2];
    const float* start_state = (const float*)d_in[3];
    const float* ln1_g = (const float*)d_in[4];
    const float* ln1_b = (const float*)d_in[5];
    const float* qkv_w = (const float*)d_in[6];
    const float* qkv_b = (const float*)d_in[7];
    const float* out_w = (const float*)d_in[8];
    const float* out_b = (const float*)d_in[9];
    const float* ln2_g = (const float*)d_in[10];
    const float* ln2_b = (const float*)d_in[11];
    const float* ff1_w = (const float*)d_in[12];
    const float* ff1_b = (const float*)d_in[13];
    const float* ff2_w = (const float*)d_in[14];
    const float* ff2_b = (const float*)d_in[15];
    const float* head_w = (const float*)d_in[16];
    const float* head_b = (const float*)d_in[17];
    float* out = (float*)d_out;

    const int smem = SMEM_F * (int)sizeof(float);
    static int configured = 0;
    if (!configured) {
        cudaFuncSetAttribute(persistent_kernel, cudaFuncAttributeMaxDynamicSharedMemorySize, smem);
        configured = 1;
    }

    persistent_kernel<<<GBLK, GTHR, smem>>>(a_seq, b_seq, bit_emb, start_state, ln1_g, ln1_b,
                                            qkv_w, qkv_b, out_w, out_b, ln2_g, ln2_b, ff1_w,
                                            ff1_b, ff2_w, ff2_b, head_w, head_b, out);
}

// round 8
// speedup vs baseline: 2.2875x; 1.4401x over previous
#include <cuda_runtime.h>
#include <cstdint>

#define NB 4096
#define NS 64
#define ND 512
#define NDEPTH 4
#define LN_EPS 1e-5f

#define BM 128
#define BN 128
#define BK 32      // 32 k-values = 16 packed words per ktile
#define ASTR 20    // A smem row stride in words (16 data + 4 pad)
#define BSTR 136   // B smem row stride in words (128 data + 8 pad)

#define GBLK 256
#define GTHR 256

#define A_ST_W (BM * ASTR)             // 2560 words per A stage
#define W_ST_W (16 * BSTR)             // 2176 words per B stage
#define W_OFF_W (3 * A_ST_W)           // 7680
#define SMEM_W (W_OFF_W + 3 * W_ST_W)  // 14208 words = 56832 B

#define F_RAW 0
#define F_EPI 1  // bias + relu + pack-to-bf16 (ff1 -> h)

// Activation scratch
static __device__ __align__(128) float g_x[NB * ND];           // residual (fp32)
static __device__ __align__(128) uint32_t g_yp[NB * ND / 2];   // LN out, bf16x2 packed
static __device__ __align__(128) uint32_t g_hp[NB * 2 * ND];   // ff1 out, bf16x2 packed
static __device__ __align__(128) float g_p0[NB * ND];          // split-K partial 0
static __device__ __align__(128) float g_p1[NB * ND];          // split-K partial 1
// Packed weights: word (kk, n) = (bf16 W[2kk][n], bf16 W[2kk+1][n])
static __device__ __align__(128) uint32_t g_wcp[NDEPTH * (ND / 2) * ND];
static __device__ __align__(128) uint32_t g_w1p[NDEPTH * (ND / 2) * 4 * ND];
static __device__ __align__(128) uint32_t g_w2p[NDEPTH * 2 * ND * ND];
static __device__ float g_bc[NDEPTH * ND];  // bv @ Wo + bo (fp32)

static __device__ unsigned g_bar = 0;
static __device__ volatile unsigned g_epoch = 0;

__device__ __forceinline__ void grid_bar() {
    __threadfence();
    __syncthreads();
    if (threadIdx.x == 0) {
        unsigned e = g_epoch;
        if (atomicAdd(&g_bar, 1u) == GBLK - 1) {
            g_bar = 0;
            __threadfence();
            g_epoch = e + 1;
        } else {
            while (g_epoch == e) __nanosleep(32);
            __threadfence();
        }
    }
    __syncthreads();
}

__device__ __forceinline__ float warp_sum(float v) {
#pragma unroll
    for (int o = 16; o > 0; o >>= 1) v += __shfl_xor_sync(0xffffffffu, v, o);
    return v;
}

// pack two f32 -> bf16x2 word (lo = first arg), round-to-nearest-even
__device__ __forceinline__ uint32_t pkbf(float lo, float hi) {
    uint32_t r;
    asm("cvt.rn.bf16x2.f32 %0, %1, %2;" : "=r"(r) : "f"(hi), "f"(lo));
    return r;
}

__device__ __forceinline__ void cpasync16(void* smem, const void* gmem) {
    uint32_t sa = (uint32_t)__cvta_generic_to_shared(smem);
    asm volatile("cp.async.cg.shared.global [%0], [%1], 16;\n" ::"r"(sa), "l"(gmem));
}

// ---------------------------------------------------------------------------
// One-time prep: Wc = Wv @ Wo (fp32) packed to bf16 pairs; bc; pack ff1/ff2.
// ---------------------------------------------------------------------------
__device__ void prep_phase(const float* __restrict__ qkv_w, const float* __restrict__ qkv_b,
                           const float* __restrict__ out_w, const float* __restrict__ out_b,
                           const float* __restrict__ ff1_w, const float* __restrict__ ff2_w) {
    const int gtid = blockIdx.x * GTHR + threadIdx.x;
    const int stride = GBLK * GTHR;
    // g_wcp word (l, kk, n): dots for k = 2kk, 2kk+1
    for (int i = gtid; i < NDEPTH * (ND / 2) * ND; i += stride) {
        int n = i & (ND - 1), kk = (i >> 9) & (ND / 2 - 1), l = i >> 17;
        const float* wv0 = qkv_w + ((size_t)l * ND + 2 * kk) * (3 * ND) + 2 * ND;
        const float* wv1 = wv0 + 3 * ND;
        const float* wo = out_w + (size_t)l * ND * ND + n;
        float s0 = 0.f, s1 = 0.f;
#pragma unroll 4
        for (int j = 0; j < ND; j++) {
            float w = wo[(size_t)j * ND];
            s0 += wv0[j] * w;
            s1 += wv1[j] * w;
        }
        g_wcp[i] = pkbf(s0, s1);
    }
    for (int i = gtid; i < NDEPTH * ND; i += stride) {
        int n = i & (ND - 1), l = i >> 9;
        const float* bv = qkv_b + l * 3 * ND + 2 * ND;
        const float* wo = out_w + (size_t)l * ND * ND + n;
        float s = out_b[l * ND + n];
#pragma unroll 4
        for (int j = 0; j < ND; j++) s += bv[j] * wo[(size_t)j * ND];
        g_bc[i] = s;
    }
    for (int i = gtid; i < NDEPTH * (ND / 2) * 4 * ND; i += stride) {
        int n = i & (4 * ND - 1), kk = (i >> 11) & (ND / 2 - 1), l = i >> 19;
        size_t base = ((size_t)l * ND + 2 * kk) * (4 * ND) + n;
        g_w1p[i] = pkbf(ff1_w[base], ff1_w[base + 4 * ND]);
    }
    for (int i = gtid; i < NDEPTH * 2 * ND * ND; i += stride) {
        int n = i & (ND - 1), kk = (i >> 9) & (2 * ND - 1), l = i >> 19;
        size_t base = ((size_t)l * 4 * ND + 2 * kk) * ND + n;
        g_w2p[i] = pkbf(ff2_w[base], ff2_w[base + ND]);
    }
}

// ---------------------------------------------------------------------------
// Elementwise phases (warp per row)
// ---------------------------------------------------------------------------
__device__ void emb0_phase(const int* __restrict__ a_seq, const int* __restrict__ b_seq,
                           const float* __restrict__ emb, const float* __restrict__ start) {
    int gw = blockIdx.x * 8 + (threadIdx.x >> 5);
    int lane = threadIdx.x & 31;
    for (int row = gw; row < NB; row += GBLK * 8) {
        int a = a_seq[row * NS];
        int b = b_seq[row * NS];
        const float4* ea = (const float4*)(emb + (size_t)a * ND);
        const float4* eb = (const float4*)(emb + (size_t)b * ND);
        const float4* ss = (const float4*)start;
        float4* xr = (float4*)(g_x + (size_t)row * ND);
#pragma unroll
        for (int j = 0; j < 4; j++) {
            int c = lane + 32 * j;
            float4 va = ea[c], vb = eb[c], vs = ss[c];
            float4 o;
            o.x = va.x + vb.x + vs.x;
            o.y = va.y + vb.y + vs.y;
            o.z = va.z + vb.z + vs.z;
            o.w = va.w + vb.w + vs.w;
            xr[c] = o;
        }
    }
}

// LN: optional fused split-K reduce (x += p0+p1+addb), writes y packed bf16x2.
template <bool FUSE>
__device__ void ln_phase(float* __restrict__ x, uint32_t* __restrict__ yp,
                         const float* __restrict__ p0, const float* __restrict__ p1,
                         const float* __restrict__ addb, const float* __restrict__ g,
                         const float* __restrict__ b) {
    int gw = blockIdx.x * 8 + (threadIdx.x >> 5);
    int lane = threadIdx.x & 31;
    for (int row = gw; row < NB; row += GBLK * 8) {
        float4* xr = (float4*)(x + (size_t)row * ND);
        float4 v[4];
        float s = 0.f;
#pragma unroll
        for (int j = 0; j < 4; j++) {
            int c = lane + 32 * j;
            v[j] = xr[c];
            if (FUSE) {
                float4 a0 = ((const float4*)(p0 + (size_t)row * ND))[c];
                float4 a1 = ((const float4*)(p1 + (size_t)row * ND))[c];
                float4 ab = ((const float4*)addb)[c];
                v[j].x += a0.x + a1.x + ab.x;
                v[j].y += a0.y + a1.y + ab.y;
                v[j].z += a0.z + a1.z + ab.z;
                v[j].w += a0.w + a1.w + ab.w;
                xr[c] = v[j];
            }
            s += v[j].x + v[j].y + v[j].z + v[j].w;
        }
        s = warp_sum(s);
        float mean = s * (1.0f / ND);
        float q = 0.f;
#pragma unroll
        for (int j = 0; j < 4; j++) {
            float cx = v[j].x - mean, cy = v[j].y - mean;
            float cz = v[j].z - mean, cw = v[j].w - mean;
            q += cx * cx + cy * cy + cz * cz + cw * cw;
        }
        q = warp_sum(q);
        float r = rsqrtf(q * (1.0f / ND) + LN_EPS);
        uint2* yr = (uint2*)(yp + (size_t)row * (ND / 2));
#pragma unroll
        for (int j = 0; j < 4; j++) {
            int c = lane + 32 * j;
            float4 gg = ((const float4*)g)[c];
            float4 bb = ((const float4*)b)[c];
            uint2 o;
            o.x = pkbf((v[j].x - mean) * r * gg.x + bb.x, (v[j].y - mean) * r * gg.y + bb.y);
            o.y = pkbf((v[j].z - mean) * r * gg.z + bb.z, (v[j].w - mean) * r * gg.w + bb.w);
            yr[c] = o;
        }
    }
}

// Head with fused ff2 reduce: x += p0+p1+b2; logits; x += emb(t+1).
__device__ void heademb_phase(const float* __restrict__ p0, const float* __restrict__ p1,
                              const float* __restrict__ addb, const float* __restrict__ hw,
                              const float* __restrict__ hb, float* __restrict__ out,
                              const int* __restrict__ a_seq, const int* __restrict__ b_seq,
                              const float* __restrict__ emb, int t) {
    int gw = blockIdx.x * 8 + (threadIdx.x >> 5);
    int lane = threadIdx.x & 31;
    for (int row = gw; row < NB; row += GBLK * 8) {
        float4* xr = (float4*)(g_x + (size_t)row * ND);
        float4 v[4];
        float s0 = 0.f, s1 = 0.f;
#pragma unroll
        for (int j = 0; j < 4; j++) {
            int c = lane + 32 * j;
            v[j] = xr[c];
            float4 a0 = ((const float4*)(p0 + (size_t)row * ND))[c];
            float4 a1 = ((const float4*)(p1 + (size_t)row * ND))[c];
            float4 ab = ((const float4*)addb)[c];
            v[j].x += a0.x + a1.x + ab.x;
            v[j].y += a0.y + a1.y + ab.y;
            v[j].z += a0.z + a1.z + ab.z;
            v[j].w += a0.w + a1.w + ab.w;
#pragma unroll
            for (int u = 0; u < 4; u++) {
                float xv = (&v[j].x)[u];
                float2 w = ((const float2*)hw)[c * 4 + u];
                s0 += xv * w.x;
                s1 += xv * w.y;
            }
        }
        s0 = warp_sum(s0);
        s1 = warp_sum(s1);
        if (lane == 0) {
            out[(size_t)row * NS * 2 + t * 2 + 0] = s0 + hb[0];
            out[(size_t)row * NS * 2 + t * 2 + 1] = s1 + hb[1];
        }
        if (t + 1 < NS) {
            int a = a_seq[row * NS + t + 1];
            int b = b_seq[row * NS + t + 1];
            const float4* ea = (const float4*)(emb + (size_t)a * ND);
            const float4* eb = (const float4*)(emb + (size_t)b * ND);
#pragma unroll
            for (int j = 0; j < 4; j++) {
                int c = lane + 32 * j;
                v[j].x += ea[c].x + eb[c].x;
                v[j].y += ea[c].y + eb[c].y;
                v[j].z += ea[c].z + eb[c].z;
                v[j].w += ea[c].w + eb[c].w;
                xr[c] = v[j];
            }
        } else {
#pragma unroll
            for (int j = 0; j < 4; j++) xr[lane + 32 * j] = v[j];
        }
    }
}

// ---------------------------------------------------------------------------
// BF16 GEMM: block tile 128x128, 8 warps 4x2, warp tile 32x64,
// mma.m16n8k16.bf16 (fp32 acc), 3-stage cp.async, split-K support.
// A: packed bf16x2 [M][Kw] words. W: packed [Kw][N] words.
// F_RAW: partials fp32 to C0/C1.  F_EPI: C0p = pack(relu(acc + bias)).
// ---------------------------------------------------------------------------
template <int FLAGS>
__device__ void gemm_phase(const uint32_t* __restrict__ Aw, int Kw,
                           const uint32_t* __restrict__ Wp, int ldw,
                           const float* __restrict__ bias, float* __restrict__ C0,
                           float* __restrict__ C1, uint32_t* __restrict__ C0p, int N, int KT,
                           int nsplit, uint32_t* sm) {
    uint32_t* sA = sm;
    uint32_t* sW = sm + W_OFF_W;

    const int tid = threadIdx.x;
    const int warp = tid >> 5, lane = tid & 31;
    const int wm = warp >> 1, wn = warp & 1;  // 4 x 2 warp grid
    const int gid = lane >> 2, tig = lane & 3;

    const int ar0 = wm * 32 + gid;
    const int bcol = wn * 64 + gid;

    const int nT = N / BN;
    const int njobs = (NB / BM) * nT * nsplit;

    for (int job = blockIdx.x; job < njobs; job += GBLK) {
        const int split = job / ((NB / BM) * nT);
        const int rr = job - split * (NB / BM) * nT;
        const int bm = rr / nT, bn = rr % nT;
        const int k0w = split * KT * 16;
        const uint32_t* Ag = Aw + (size_t)bm * BM * Kw + k0w;
        const uint32_t* Wg = Wp + (size_t)k0w * ldw + bn * BN;
        float* C = split ? C1 : C0;

        float acc[2][8][4];
#pragma unroll
        for (int i = 0; i < 2; i++)
#pragma unroll
            for (int j = 0; j < 8; j++)
#pragma unroll
                for (int k = 0; k < 4; k++) acc[i][j][k] = 0.f;

        auto load_tiles = [&](int kt, int st) {
            uint32_t* dA = sA + st * A_ST_W;
            const uint32_t* srcA = Ag + kt * 16;
#pragma unroll
            for (int i = 0; i < 2; i++) {
                int c = tid + i * 256;
                int row = c >> 2, ch = c & 3;
                cpasync16(dA + row * ASTR + ch * 4, srcA + (size_t)row * Kw + ch * 4);
            }
            uint32_t* dW = sW + st * W_ST_W;
            const uint32_t* srcW = Wg + (size_t)kt * 16 * ldw;
#pragma unroll
            for (int i = 0; i < 2; i++) {
                int c = tid + i * 256;
                int row = c >> 5, ch = c & 31;
                cpasync16(dW + row * BSTR + ch * 4, srcW + (size_t)row * ldw + ch * 4);
            }
            asm volatile("cp.async.commit_group;\n");
        };

        load_tiles(0, 0);
        load_tiles(1, 1);

        int st = 0;
        for (int kt = 0; kt < KT; ++kt, st = (st == 2) ? 0 : st + 1) {
            if (kt == KT - 1) {
                asm volatile("cp.async.wait_group 0;\n");
            } else {
                asm volatile("cp.async.wait_group 1;\n");
            }
            __syncthreads();
            if (kt + 2 < KT) {
                int st2 = st + 2;
                if (st2 >= 3) st2 -= 3;
                load_tiles(kt + 2, st2);
            }
            const uint32_t* a_ = sA + st * A_ST_W;
            const uint32_t* w_ = sW + st * W_ST_W;
#pragma unroll
            for (int ks = 0; ks < 2; ++ks) {
                const int acol = ks * 8 + tig;
                uint32_t af[2][4];
#pragma unroll
                for (int mi = 0; mi < 2; ++mi) {
                    const int r0 = (ar0 + mi * 16) * ASTR;
                    const int r1 = r0 + 8 * ASTR;
                    af[mi][0] = a_[r0 + acol];
                    af[mi][1] = a_[r1 + acol];
                    af[mi][2] = a_[r0 + acol + 4];
                    af[mi][3] = a_[r1 + acol + 4];
                }
                const int brow = (ks * 8 + tig) * BSTR + bcol;
#pragma unroll
                for (int ni = 0; ni < 8; ++ni) {
                    uint32_t b0 = w_[brow + ni * 8];
                    uint32_t b1 = w_[brow + 4 * BSTR + ni * 8];
#pragma unroll
                    for (int mi = 0; mi < 2; ++mi) {
                        asm volatile(
                            "mma.sync.aligned.m16n8k16.row.col.f32.bf16.bf16.f32 "
                            "{%0,%1,%2,%3},{%4,%5,%6,%7},{%8,%9},{%0,%1,%2,%3};\n"
                            : "+f"(acc[mi][ni][0]), "+f"(acc[mi][ni][1]),
                              "+f"(acc[mi][ni][2]), "+f"(acc[mi][ni][3])
                            : "r"(af[mi][0]), "r"(af[mi][1]), "r"(af[mi][2]), "r"(af[mi][3]),
                              "r"(b0), "r"(b1));
                    }
                }
            }
        }

#pragma unroll
        for (int mi = 0; mi < 2; mi++) {
            int row0 = bm * BM + wm * 32 + mi * 16 + gid;
#pragma unroll
            for (int ni = 0; ni < 8; ni++) {
                int col = bn * BN + wn * 64 + ni * 8 + tig * 2;
                if (FLAGS == F_EPI) {
                    float2 bv = *(const float2*)(bias + col);
                    float x0 = fmaxf(acc[mi][ni][0] + bv.x, 0.f);
                    float y0 = fmaxf(acc[mi][ni][1] + bv.y, 0.f);
                    float x1 = fmaxf(acc[mi][ni][2] + bv.x, 0.f);
                    float y1 = fmaxf(acc[mi][ni][3] + bv.y, 0.f);
                    C0p[(size_t)row0 * (N / 2) + (col >> 1)] = pkbf(x0, y0);
                    C0p[(size_t)(row0 + 8) * (N / 2) + (col >> 1)] = pkbf(x1, y1);
                } else {
                    float2 v0, v1;
                    v0.x = acc[mi][ni][0];
                    v0.y = acc[mi][ni][1];
                    v1.x = acc[mi][ni][2];
                    v1.y = acc[mi][ni][3];
                    *(float2*)(C + (size_t)row0 * N + col) = v0;
                    *(float2*)(C + (size_t)(row0 + 8) * N + col) = v1;
                }
            }
        }
        __syncthreads();
    }
}

// ---------------------------------------------------------------------------
// Persistent kernel
// ---------------------------------------------------------------------------
__global__ __launch_bounds__(GTHR, 2) void persistent_kernel(
    const int* __restrict__ a_seq, const int* __restrict__ b_seq,
    const float* __restrict__ bit_emb, const float* __restrict__ start_state,
    const float* __restrict__ ln1_g, const float* __restrict__ ln1_b,
    const float* __restrict__ qkv_w, const float* __restrict__ qkv_b,
    const float* __restrict__ out_w, const float* __restrict__ out_b,
    const float* __restrict__ ln2_g, const float* __restrict__ ln2_b,
    const float* __restrict__ ff1_w, const float* __restrict__ ff1_b,
    const float* __restrict__ ff2_w, const float* __restrict__ ff2_b,
    const float* __restrict__ head_w, const float* __restrict__ head_b, float* __restrict__ out) {
    extern __shared__ uint32_t sm[];

    prep_phase(qkv_w, qkv_b, out_w, out_b, ff1_w, ff2_w);
    emb0_phase(a_seq, b_seq, bit_emb, start_state);
    grid_bar();

    for (int t = 0; t < NS; ++t) {
        for (int l = 0; l < NDEPTH; ++l) {
            // LN1: plain at l==0; else fuse ff2 reduce of l-1
            if (l == 0)
                ln_phase<false>(g_x, g_yp, nullptr, nullptr, nullptr, ln1_g + l * ND,
                                ln1_b + l * ND);
            else
                ln_phase<true>(g_x, g_yp, g_p0, g_p1, ff2_b + (size_t)(l - 1) * ND,
                               ln1_g + l * ND, ln1_b + l * ND);
            grid_bar();
            // Wc GEMM (split-K 2): p0/p1 = y @ Wc
            gemm_phase<F_RAW>(g_yp, ND / 2, g_wcp + (size_t)l * (ND / 2) * ND, ND, nullptr,
                              g_p0, g_p1, nullptr, ND, 8, 2, sm);
            grid_bar();
            // LN2 fused: x += p0+p1+bc; y = LN2(x) packed
            ln_phase<true>(g_x, g_yp, g_p0, g_p1, g_bc + l * ND, ln2_g + l * ND,
                           ln2_b + l * ND);
            grid_bar();
            // h = pack(relu(y @ W1 + b1))
            gemm_phase<F_EPI>(g_yp, ND / 2, g_w1p + (size_t)l * (ND / 2) * 4 * ND, 4 * ND,
                              ff1_b + (size_t)l * 4 * ND, nullptr, nullptr, g_hp, 4 * ND, 16, 1,
                              sm);
            grid_bar();
            // ff2 GEMM (split-K 2): p0/p1 = h @ W2
            gemm_phase<F_RAW>(g_hp, 2 * ND, g_w2p + (size_t)l * 2 * ND * ND, ND, nullptr, g_p0,
                              g_p1, nullptr, ND, 32, 2, sm);
            grid_bar();
        }
        heademb_phase(g_p0, g_p1, ff2_b + (size_t)(NDEPTH - 1) * ND, head_w, head_b, out, a_seq,
                      b_seq, bit_emb, t);
        grid_bar();
    }
}

// ---------------------------------------------------------------------------
extern "C" void kernel_launch(void* const* d_in, const int* in_sizes, int n_in,
                              void* d_out, int out_size) {
    const int* a_seq = (const int*)d_in[0];
    const int* b_seq = (const int*)d_in[1];
    const float* bit_emb = (const float*)d_in[2];
    const float* start_state = (const float*)d_in[3];
    const float* ln1_g = (const float*)d_in[4];
    const float* ln1_b = (const float*)d_in[5];
    const float* qkv_w = (const float*)d_in[6];
    const float* qkv_b = (const float*)d_in[7];
    const float* out_w = (const float*)d_in[8];
    const float* out_b = (const float*)d_in[9];
    const float* ln2_g = (const float*)d_in[10];
    const float* ln2_b = (const float*)d_in[11];
    const float* ff1_w = (const float*)d_in[12];
    const float* ff1_b = (const float*)d_in[13];
    const float* ff2_w = (const float*)d_in[14];
    const float* ff2_b = (const float*)d_in[15];
    const float* head_w = (const float*)d_in[16];
    const float* head_b = (const float*)d_in[17];
    float* out = (float*)d_out;

    const int smem = SMEM_W * (int)sizeof(uint32_t);
    static int configured = 0;
    if (!configured) {
        cudaFuncSetAttribute(persistent_kernel, cudaFuncAttributeMaxDynamicSharedMemorySize, smem);
        configured = 1;
    }

    persistent_kernel<<<GBLK, GTHR, smem>>>(a_seq, b_seq, bit_emb, start_state, ln1_g, ln1_b,
                                            qkv_w, qkv_b, out_w, out_b, ln2_g, ln2_b, ff1_w,
                                            ff1_b, ff2_w, ff2_b, head_w, head_b, out);
}

// round 9
// speedup vs baseline: 2.4658x; 1.0779x over previous
#include <cuda_runtime.h>
#include <cstdint>

#define NB 4096
#define NS 64
#define ND 512
#define NDEPTH 4
#define LN_EPS 1e-5f

#define BM 128
#define BN 128
#define KTW 32     // packed words per ktile (= 64 k-values)
#define ASTR 36    // A smem row stride in words (32 data + 4 pad)
#define BSTR 136   // B smem row stride in words (128 data + 8 pad)

#define GBLK 256
#define GTHR 256

#define A_ST_W (BM * ASTR)             // 4608 words per A stage
#define W_ST_W (KTW * BSTR)            // 4352 words per B stage
#define W_OFF_W (3 * A_ST_W)           // 13824
#define SMEM_W (W_OFF_W + 3 * W_ST_W)  // 26880 words = 107520 B

#define F_RAW 0
#define F_EPI 1  // bias + relu + pack-to-bf16 (ff1 -> h)

// Activation scratch
static __device__ __align__(128) float g_x[NB * ND];           // residual (fp32)
static __device__ __align__(128) uint32_t g_yp[NB * ND / 2];   // LN out, bf16x2 packed
static __device__ __align__(128) uint32_t g_hp[NB * 2 * ND];   // ff1 out, bf16x2 packed
static __device__ __align__(128) float g_p0[NB * ND];          // split-K partial 0
static __device__ __align__(128) float g_p1[NB * ND];          // split-K partial 1
// Packed weights: word (kk, n) = (bf16 W[2kk][n], bf16 W[2kk+1][n])
static __device__ __align__(128) uint32_t g_wcp[NDEPTH * (ND / 2) * ND];
static __device__ __align__(128) uint32_t g_w1p[NDEPTH * (ND / 2) * 4 * ND];
static __device__ __align__(128) uint32_t g_w2p[NDEPTH * 2 * ND * ND];
static __device__ float g_bc[NDEPTH * ND];  // bv @ Wo + bo (fp32)

static __device__ unsigned g_bar = 0;
static __device__ volatile unsigned g_epoch = 0;

__device__ __forceinline__ void grid_bar() {
    __threadfence();
    __syncthreads();
    if (threadIdx.x == 0) {
        unsigned e = g_epoch;
        if (atomicAdd(&g_bar, 1u) == GBLK - 1) {
            g_bar = 0;
            __threadfence();
            g_epoch = e + 1;
        } else {
            while (g_epoch == e) __nanosleep(32);
            __threadfence();
        }
    }
    __syncthreads();
}

__device__ __forceinline__ float warp_sum(float v) {
#pragma unroll
    for (int o = 16; o > 0; o >>= 1) v += __shfl_xor_sync(0xffffffffu, v, o);
    return v;
}

// pack two f32 -> bf16x2 word (lo = first arg), round-to-nearest-even
__device__ __forceinline__ uint32_t pkbf(float lo, float hi) {
    uint32_t r;
    asm("cvt.rn.bf16x2.f32 %0, %1, %2;" : "=r"(r) : "f"(hi), "f"(lo));
    return r;
}

__device__ __forceinline__ void cpasync16(void* smem, const void* gmem) {
    uint32_t sa = (uint32_t)__cvta_generic_to_shared(smem);
    asm volatile("cp.async.cg.shared.global [%0], [%1], 16;\n" ::"r"(sa), "l"(gmem));
}

// ---------------------------------------------------------------------------
// One-time prep: Wc = Wv @ Wo (fp32) packed to bf16 pairs; bc; pack ff1/ff2.
// ---------------------------------------------------------------------------
__device__ void prep_phase(const float* __restrict__ qkv_w, const float* __restrict__ qkv_b,
                           const float* __restrict__ out_w, const float* __restrict__ out_b,
                           const float* __restrict__ ff1_w, const float* __restrict__ ff2_w) {
    const int gtid = blockIdx.x * GTHR + threadIdx.x;
    const int stride = GBLK * GTHR;
    for (int i = gtid; i < NDEPTH * (ND / 2) * ND; i += stride) {
        int n = i & (ND - 1), kk = (i >> 9) & (ND / 2 - 1), l = i >> 17;
        const float* wv0 = qkv_w + ((size_t)l * ND + 2 * kk) * (3 * ND) + 2 * ND;
        const float* wv1 = wv0 + 3 * ND;
        const float* wo = out_w + (size_t)l * ND * ND + n;
        float s0 = 0.f, s1 = 0.f;
#pragma unroll 4
        for (int j = 0; j < ND; j++) {
            float w = wo[(size_t)j * ND];
            s0 += wv0[j] * w;
            s1 += wv1[j] * w;
        }
        g_wcp[i] = pkbf(s0, s1);
    }
    for (int i = gtid; i < NDEPTH * ND; i += stride) {
        int n = i & (ND - 1), l = i >> 9;
        const float* bv = qkv_b + l * 3 * ND + 2 * ND;
        const float* wo = out_w + (size_t)l * ND * ND + n;
        float s = out_b[l * ND + n];
#pragma unroll 4
        for (int j = 0; j < ND; j++) s += bv[j] * wo[(size_t)j * ND];
        g_bc[i] = s;
    }
    for (int i = gtid; i < NDEPTH * (ND / 2) * 4 * ND; i += stride) {
        int n = i & (4 * ND - 1), kk = (i >> 11) & (ND / 2 - 1), l = i >> 19;
        size_t base = ((size_t)l * ND + 2 * kk) * (4 * ND) + n;
        g_w1p[i] = pkbf(ff1_w[base], ff1_w[base + 4 * ND]);
    }
    for (int i = gtid; i < NDEPTH * 2 * ND * ND; i += stride) {
        int n = i & (ND - 1), kk = (i >> 9) & (2 * ND - 1), l = i >> 19;
        size_t base = ((size_t)l * 4 * ND + 2 * kk) * ND + n;
        g_w2p[i] = pkbf(ff2_w[base], ff2_w[base + ND]);
    }
}

// ---------------------------------------------------------------------------
// Elementwise phases (warp per row)
// ---------------------------------------------------------------------------
__device__ void emb0_phase(const int* __restrict__ a_seq, const int* __restrict__ b_seq,
                           const float* __restrict__ emb, const float* __restrict__ start) {
    int gw = blockIdx.x * 8 + (threadIdx.x >> 5);
    int lane = threadIdx.x & 31;
    for (int row = gw; row < NB; row += GBLK * 8) {
        int a = a_seq[row * NS];
        int b = b_seq[row * NS];
        const float4* ea = (const float4*)(emb + (size_t)a * ND);
        const float4* eb = (const float4*)(emb + (size_t)b * ND);
        const float4* ss = (const float4*)start;
        float4* xr = (float4*)(g_x + (size_t)row * ND);
#pragma unroll
        for (int j = 0; j < 4; j++) {
            int c = lane + 32 * j;
            float4 va = ea[c], vb = eb[c], vs = ss[c];
            float4 o;
            o.x = va.x + vb.x + vs.x;
            o.y = va.y + vb.y + vs.y;
            o.z = va.z + vb.z + vs.z;
            o.w = va.w + vb.w + vs.w;
            xr[c] = o;
        }
    }
}

// LN: optional fused split-K reduce (x += p0+p1+addb), writes y packed bf16x2.
template <bool FUSE>
__device__ void ln_phase(float* __restrict__ x, uint32_t* __restrict__ yp,
                         const float* __restrict__ p0, const float* __restrict__ p1,
                         const float* __restrict__ addb, const float* __restrict__ g,
                         const float* __restrict__ b) {
    int gw = blockIdx.x * 8 + (threadIdx.x >> 5);
    int lane = threadIdx.x & 31;
    for (int row = gw; row < NB; row += GBLK * 8) {
        float4* xr = (float4*)(x + (size_t)row * ND);
        float4 v[4];
        float s = 0.f;
#pragma unroll
        for (int j = 0; j < 4; j++) {
            int c = lane + 32 * j;
            v[j] = xr[c];
            if (FUSE) {
                float4 a0 = ((const float4*)(p0 + (size_t)row * ND))[c];
                float4 a1 = ((const float4*)(p1 + (size_t)row * ND))[c];
                float4 ab = ((const float4*)addb)[c];
                v[j].x += a0.x + a1.x + ab.x;
                v[j].y += a0.y + a1.y + ab.y;
                v[j].z += a0.z + a1.z + ab.z;
                v[j].w += a0.w + a1.w + ab.w;
                xr[c] = v[j];
            }
            s += v[j].x + v[j].y + v[j].z + v[j].w;
        }
        s = warp_sum(s);
        float mean = s * (1.0f / ND);
        float q = 0.f;
#pragma unroll
        for (int j = 0; j < 4; j++) {
            float cx = v[j].x - mean, cy = v[j].y - mean;
            float cz = v[j].z - mean, cw = v[j].w - mean;
            q += cx * cx + cy * cy + cz * cz + cw * cw;
        }
        q = warp_sum(q);
        float r = rsqrtf(q * (1.0f / ND) + LN_EPS);
        uint2* yr = (uint2*)(yp + (size_t)row * (ND / 2));
#pragma unroll
        for (int j = 0; j < 4; j++) {
            int c = lane + 32 * j;
            float4 gg = ((const float4*)g)[c];
            float4 bb = ((const float4*)b)[c];
            uint2 o;
            o.x = pkbf((v[j].x - mean) * r * gg.x + bb.x, (v[j].y - mean) * r * gg.y + bb.y);
            o.y = pkbf((v[j].z - mean) * r * gg.z + bb.z, (v[j].w - mean) * r * gg.w + bb.w);
            yr[c] = o;
        }
    }
}

// Head with fused ff2 reduce: x += p0+p1+b2; logits; x += emb(t+1).
__device__ void heademb_phase(const float* __restrict__ p0, const float* __restrict__ p1,
                              const float* __restrict__ addb, const float* __restrict__ hw,
                              const float* __restrict__ hb, float* __restrict__ out,
                              const int* __restrict__ a_seq, const int* __restrict__ b_seq,
                              const float* __restrict__ emb, int t) {
    int gw = blockIdx.x * 8 + (threadIdx.x >> 5);
    int lane = threadIdx.x & 31;
    for (int row = gw; row < NB; row += GBLK * 8) {
        float4* xr = (float4*)(g_x + (size_t)row * ND);
        float4 v[4];
        float s0 = 0.f, s1 = 0.f;
#pragma unroll
        for (int j = 0; j < 4; j++) {
            int c = lane + 32 * j;
            v[j] = xr[c];
            float4 a0 = ((const float4*)(p0 + (size_t)row * ND))[c];
            float4 a1 = ((const float4*)(p1 + (size_t)row * ND))[c];
            float4 ab = ((const float4*)addb)[c];
            v[j].x += a0.x + a1.x + ab.x;
            v[j].y += a0.y + a1.y + ab.y;
            v[j].z += a0.z + a1.z + ab.z;
            v[j].w += a0.w + a1.w + ab.w;
#pragma unroll
            for (int u = 0; u < 4; u++) {
                float xv = (&v[j].x)[u];
                float2 w = ((const float2*)hw)[c * 4 + u];
                s0 += xv * w.x;
                s1 += xv * w.y;
            }
        }
        s0 = warp_sum(s0);
        s1 = warp_sum(s1);
        if (lane == 0) {
            out[(size_t)row * NS * 2 + t * 2 + 0] = s0 + hb[0];
            out[(size_t)row * NS * 2 + t * 2 + 1] = s1 + hb[1];
        }
        if (t + 1 < NS) {
            int a = a_seq[row * NS + t + 1];
            int b = b_seq[row * NS + t + 1];
            const float4* ea = (const float4*)(emb + (size_t)a * ND);
            const float4* eb = (const float4*)(emb + (size_t)b * ND);
#pragma unroll
            for (int j = 0; j < 4; j++) {
                int c = lane + 32 * j;
                v[j].x += ea[c].x + eb[c].x;
                v[j].y += ea[c].y + eb[c].y;
                v[j].z += ea[c].z + eb[c].z;
                v[j].w += ea[c].w + eb[c].w;
                xr[c] = v[j];
            }
        } else {
#pragma unroll
            for (int j = 0; j < 4; j++) xr[lane + 32 * j] = v[j];
        }
    }
}

// ---------------------------------------------------------------------------
// BF16 GEMM: block tile 128x128, warp tile 32x64, mma.m16n8k16 (fp32 acc),
// ktile = 64 k-values (32 words), 3-stage cp.async, 1 sync per ktile,
// 64 HMMA per warp per sync window. Split-K support.
// ---------------------------------------------------------------------------
template <int FLAGS>
__device__ void gemm_phase(const uint32_t* __restrict__ Aw, int Kw,
                           const uint32_t* __restrict__ Wp, int ldw,
                           const float* __restrict__ bias, float* __restrict__ C0,
                           float* __restrict__ C1, uint32_t* __restrict__ C0p, int N, int KT,
                           int nsplit, uint32_t* sm) {
    uint32_t* sA = sm;
    uint32_t* sW = sm + W_OFF_W;

    const int tid = threadIdx.x;
    const int warp = tid >> 5, lane = tid & 31;
    const int wm = warp >> 1, wn = warp & 1;  // 4 x 2 warp grid
    const int gid = lane >> 2, tig = lane & 3;

    const int ar0 = wm * 32 + gid;
    const int bcol = wn * 64 + gid;

    const int nT = N / BN;
    const int njobs = (NB / BM) * nT * nsplit;

    for (int job = blockIdx.x; job < njobs; job += GBLK) {
        const int split = job / ((NB / BM) * nT);
        const int rr = job - split * (NB / BM) * nT;
        const int bm = rr / nT, bn = rr % nT;
        const int k0w = split * KT * KTW;
        const uint32_t* Ag = Aw + (size_t)bm * BM * Kw + k0w;
        const uint32_t* Wg = Wp + (size_t)k0w * ldw + bn * BN;
        float* C = split ? C1 : C0;

        float acc[2][8][4];
#pragma unroll
        for (int i = 0; i < 2; i++)
#pragma unroll
            for (int j = 0; j < 8; j++)
#pragma unroll
                for (int k = 0; k < 4; k++) acc[i][j][k] = 0.f;

        auto load_tiles = [&](int kt, int st) {
            uint32_t* dA = sA + st * A_ST_W;
            const uint32_t* srcA = Ag + kt * KTW;
#pragma unroll
            for (int i = 0; i < 4; i++) {
                int c = tid + i * 256;
                int row = c >> 3, ch = c & 7;  // 8 x 16B chunks per 32-word row
                cpasync16(dA + row * ASTR + ch * 4, srcA + (size_t)row * Kw + ch * 4);
            }
            uint32_t* dW = sW + st * W_ST_W;
            const uint32_t* srcW = Wg + (size_t)kt * KTW * ldw;
#pragma unroll
            for (int i = 0; i < 4; i++) {
                int c = tid + i * 256;
                int row = c >> 5, ch = c & 31;  // 32 x 16B chunks per 128-word row
                cpasync16(dW + row * BSTR + ch * 4, srcW + (size_t)row * ldw + ch * 4);
            }
            asm volatile("cp.async.commit_group;\n");
        };

        load_tiles(0, 0);
        load_tiles(1, 1);

        int st = 0;
        for (int kt = 0; kt < KT; ++kt, st = (st == 2) ? 0 : st + 1) {
            if (kt == KT - 1) {
                asm volatile("cp.async.wait_group 0;\n");
            } else {
                asm volatile("cp.async.wait_group 1;\n");
            }
            __syncthreads();
            if (kt + 2 < KT) {
                int st2 = st + 2;
                if (st2 >= 3) st2 -= 3;
                load_tiles(kt + 2, st2);
            }
            const uint32_t* a_ = sA + st * A_ST_W;
            const uint32_t* w_ = sW + st * W_ST_W;
#pragma unroll
            for (int ks = 0; ks < 4; ++ks) {
                const int acol = ks * 8 + tig;
                uint32_t af[2][4];
#pragma unroll
                for (int mi = 0; mi < 2; ++mi) {
                    const int r0 = (ar0 + mi * 16) * ASTR;
                    const int r1 = r0 + 8 * ASTR;
                    af[mi][0] = a_[r0 + acol];
                    af[mi][1] = a_[r1 + acol];
                    af[mi][2] = a_[r0 + acol + 4];
                    af[mi][3] = a_[r1 + acol + 4];
                }
                const int brow = (ks * 8 + tig) * BSTR + bcol;
#pragma unroll
                for (int ni = 0; ni < 8; ++ni) {
                    uint32_t b0 = w_[brow + ni * 8];
                    uint32_t b1 = w_[brow + 4 * BSTR + ni * 8];
#pragma unroll
                    for (int mi = 0; mi < 2; ++mi) {
                        asm volatile(
                            "mma.sync.aligned.m16n8k16.row.col.f32.bf16.bf16.f32 "
                            "{%0,%1,%2,%3},{%4,%5,%6,%7},{%8,%9},{%0,%1,%2,%3};\n"
                            : "+f"(acc[mi][ni][0]), "+f"(acc[mi][ni][1]),
                              "+f"(acc[mi][ni][2]), "+f"(acc[mi][ni][3])
                            : "r"(af[mi][0]), "r"(af[mi][1]), "r"(af[mi][2]), "r"(af[mi][3]),
                              "r"(b0), "r"(b1));
                    }
                }
            }
        }

#pragma unroll
        for (int mi = 0; mi < 2; mi++) {
            int row0 = bm * BM + wm * 32 + mi * 16 + gid;
#pragma unroll
            for (int ni = 0; ni < 8; ni++) {
                int col = bn * BN + wn * 64 + ni * 8 + tig * 2;
                if (FLAGS == F_EPI) {
                    float2 bv = *(const float2*)(bias + col);
                    float x0 = fmaxf(acc[mi][ni][0] + bv.x, 0.f);
                    float y0 = fmaxf(acc[mi][ni][1] + bv.y, 0.f);
                    float x1 = fmaxf(acc[mi][ni][2] + bv.x, 0.f);
                    float y1 = fmaxf(acc[mi][ni][3] + bv.y, 0.f);
                    C0p[(size_t)row0 * (N / 2) + (col >> 1)] = pkbf(x0, y0);
                    C0p[(size_t)(row0 + 8) * (N / 2) + (col >> 1)] = pkbf(x1, y1);
                } else {
                    float2 v0, v1;
                    v0.x = acc[mi][ni][0];
                    v0.y = acc[mi][ni][1];
                    v1.x = acc[mi][ni][2];
                    v1.y = acc[mi][ni][3];
                    *(float2*)(C + (size_t)row0 * N + col) = v0;
                    *(float2*)(C + (size_t)(row0 + 8) * N + col) = v1;
                }
            }
        }
        __syncthreads();
    }
}

// ---------------------------------------------------------------------------
// Persistent kernel
// ---------------------------------------------------------------------------
__global__ __launch_bounds__(GTHR, 2) void persistent_kernel(
    const int* __restrict__ a_seq, const int* __restrict__ b_seq,
    const float* __restrict__ bit_emb, const float* __restrict__ start_state,
    const float* __restrict__ ln1_g, const float* __restrict__ ln1_b,
    const float* __restrict__ qkv_w, const float* __restrict__ qkv_b,
    const float* __restrict__ out_w, const float* __restrict__ out_b,
    const float* __restrict__ ln2_g, const float* __restrict__ ln2_b,
    const float* __restrict__ ff1_w, const float* __restrict__ ff1_b,
    const float* __restrict__ ff2_w, const float* __restrict__ ff2_b,
    const float* __restrict__ head_w, const float* __restrict__ head_b, float* __restrict__ out) {
    extern __shared__ uint32_t sm[];

    prep_phase(qkv_w, qkv_b, out_w, out_b, ff1_w, ff2_w);
    emb0_phase(a_seq, b_seq, bit_emb, start_state);
    grid_bar();

    for (int t = 0; t < NS; ++t) {
        for (int l = 0; l < NDEPTH; ++l) {
            // LN1: plain at l==0; else fuse ff2 reduce of l-1
            if (l == 0)
                ln_phase<false>(g_x, g_yp, nullptr, nullptr, nullptr, ln1_g + l * ND,
                                ln1_b + l * ND);
            else
                ln_phase<true>(g_x, g_yp, g_p0, g_p1, ff2_b + (size_t)(l - 1) * ND,
                               ln1_g + l * ND, ln1_b + l * ND);
            grid_bar();
            // Wc GEMM (split-K 2, KT=4 each): p0/p1 = y @ Wc
            gemm_phase<F_RAW>(g_yp, ND / 2, g_wcp + (size_t)l * (ND / 2) * ND, ND, nullptr,
                              g_p0, g_p1, nullptr, ND, 4, 2, sm);
            grid_bar();
            // LN2 fused: x += p0+p1+bc; y = LN2(x) packed
            ln_phase<true>(g_x, g_yp, g_p0, g_p1, g_bc + l * ND, ln2_g + l * ND,
                           ln2_b + l * ND);
            grid_bar();
            // h = pack(relu(y @ W1 + b1)), KT=8
            gemm_phase<F_EPI>(g_yp, ND / 2, g_w1p + (size_t)l * (ND / 2) * 4 * ND, 4 * ND,
                              ff1_b + (size_t)l * 4 * ND, nullptr, nullptr, g_hp, 4 * ND, 8, 1,
                              sm);
            grid_bar();
            // ff2 GEMM (split-K 2, KT=16 each): p0/p1 = h @ W2
            gemm_phase<F_RAW>(g_hp, 2 * ND, g_w2p + (size_t)l * 2 * ND * ND, ND, nullptr, g_p0,
                              g_p1, nullptr, ND, 16, 2, sm);
            grid_bar();
        }
        heademb_phase(g_p0, g_p1, ff2_b + (size_t)(NDEPTH - 1) * ND, head_w, head_b, out, a_seq,
                      b_seq, bit_emb, t);
        grid_bar();
    }
}

// ---------------------------------------------------------------------------
extern "C" void kernel_launch(void* const* d_in, const int* in_sizes, int n_in,
                              void* d_out, int out_size) {
    const int* a_seq = (const int*)d_in[0];
    const int* b_seq = (const int*)d_in[1];
    const float* bit_emb = (const float*)d_in[2];
    const float* start_state = (const float*)d_in[3];
    const float* ln1_g = (const float*)d_in[4];
    const float* ln1_b = (const float*)d_in[5];
    const float* qkv_w = (const float*)d_in[6];
    const float* qkv_b = (const float*)d_in[7];
    const float* out_w = (const float*)d_in[8];
    const float* out_b = (const float*)d_in[9];
    const float* ln2_g = (const float*)d_in[10];
    const float* ln2_b = (const float*)d_in[11];
    const float* ff1_w = (const float*)d_in[12];
    const float* ff1_b = (const float*)d_in[13];
    const float* ff2_w = (const float*)d_in[14];
    const float* ff2_b = (const float*)d_in[15];
    const float* head_w = (const float*)d_in[16];
    const float* head_b = (const float*)d_in[17];
    float* out = (float*)d_out;

    const int smem = SMEM_W * (int)sizeof(uint32_t);
    static int configured = 0;
    if (!configured) {
        cudaFuncSetAttribute(persistent_kernel, cudaFuncAttributeMaxDynamicSharedMemorySize, smem);
        configured = 1;
    }

    persistent_kernel<<<GBLK, GTHR, smem>>>(a_seq, b_seq, bit_emb, start_state, ln1_g, ln1_b,
                                            qkv_w, qkv_b, out_w, out_b, ln2_g, ln2_b, ff1_w,
                                            ff1_b, ff2_w, ff2_b, head_w, head_b, out);
}